// round 12
// baseline (speedup 1.0000x reference)
#include <cuda_runtime.h>
#include <cuda_bf16.h>
#include <cstdint>

// ---------------------------------------------------------------------------
// Problem constants
// ---------------------------------------------------------------------------
#define BATCHN  8
#define SEQL    1024
#define EMB     768
#define NH      12
#define HD      64
#define ROWS    (BATCHN*SEQL)        // 8192
#define QKVC    (3*EMB)              // 2304
#define ZTOT    (BATCHN*NH)          // 96
#define AROWS   (ZTOT*SEQL)          // 98304
#define K_SCALE 0.125f
#define EXP_OFF 20.0f

// ---------------------------------------------------------------------------
// Device scratch (static globals; allocation-free)
// ---------------------------------------------------------------------------
__device__ __align__(16) __nv_bfloat16 g_x_hi  [ROWS*EMB];
__device__ __align__(16) __nv_bfloat16 g_x_lo  [ROWS*EMB];
__device__ __align__(16) __nv_bfloat16 g_wqkv_hi[QKVC*EMB];
__device__ __align__(16) __nv_bfloat16 g_wqkv_lo[QKVC*EMB];
__device__ __align__(16) __nv_bfloat16 g_wp_hi [EMB*EMB];
__device__ __align__(16) __nv_bfloat16 g_wp_lo [EMB*EMB];
__device__ __align__(16) __nv_bfloat16 g_qkv_hi[(size_t)ROWS*QKVC];
__device__ __align__(16) __nv_bfloat16 g_qkv_lo[(size_t)ROWS*QKVC];
__device__ __align__(16) __nv_bfloat16 g_oh_hi [ROWS*EMB];
__device__ __align__(16) __nv_bfloat16 g_oh_lo [ROWS*EMB];
__device__ float g_psum[(size_t)AROWS*64];
__device__ float g_inv [AROWS];

// ---------------------------------------------------------------------------
// PTX helpers (all sm_80-era: safe on plain compute_103)
// ---------------------------------------------------------------------------
__device__ __forceinline__ uint32_t smem_u32(const void* p) {
    uint32_t a;
    asm("{ .reg .u64 t; cvta.to.shared.u64 t, %1; cvt.u32.u64 %0, t; }"
        : "=r"(a) : "l"(p));
    return a;
}
__device__ __forceinline__ void cp16(uint32_t dst, const void* src) {
    asm volatile("cp.async.cg.shared.global [%0], [%1], 16;"
                 :: "r"(dst), "l"(src));
}
#define CP_COMMIT() asm volatile("cp.async.commit_group;" ::: "memory")
#define CP_WAIT(n)  asm volatile("cp.async.wait_group %0;" :: "n"(n) : "memory")

__device__ __forceinline__ void ldsm_x4(uint32_t* r, uint32_t addr) {
    asm volatile("ldmatrix.sync.aligned.m8n8.x4.shared.b16 {%0,%1,%2,%3}, [%4];"
        : "=r"(r[0]), "=r"(r[1]), "=r"(r[2]), "=r"(r[3]) : "r"(addr));
}
__device__ __forceinline__ void ldsm_x2(uint32_t* r, uint32_t addr) {
    asm volatile("ldmatrix.sync.aligned.m8n8.x2.shared.b16 {%0,%1}, [%2];"
        : "=r"(r[0]), "=r"(r[1]) : "r"(addr));
}
__device__ __forceinline__ void ldsm_x2t(uint32_t* r, uint32_t addr) {
    asm volatile("ldmatrix.sync.aligned.m8n8.x2.trans.shared.b16 {%0,%1}, [%2];"
        : "=r"(r[0]), "=r"(r[1]) : "r"(addr));
}
__device__ __forceinline__ void mma_bf16(float* c, const uint32_t* a, const uint32_t* b) {
    asm volatile("mma.sync.aligned.m16n8k16.row.col.f32.bf16.bf16.f32 "
        "{%0,%1,%2,%3}, {%4,%5,%6,%7}, {%8,%9}, {%0,%1,%2,%3};"
        : "+f"(c[0]), "+f"(c[1]), "+f"(c[2]), "+f"(c[3])
        : "r"(a[0]), "r"(a[1]), "r"(a[2]), "r"(a[3]), "r"(b[0]), "r"(b[1]));
}

__device__ __forceinline__ uint32_t pack_hi(float a, float b) {
    return ((uint32_t)__bfloat16_as_ushort(__float2bfloat16(b)) << 16) |
            (uint32_t)__bfloat16_as_ushort(__float2bfloat16(a));
}
__device__ __forceinline__ uint32_t pack_lo(float a, float b) {
    __nv_bfloat16 ha = __float2bfloat16(a), hb = __float2bfloat16(b);
    float la = a - __bfloat162float(ha), lb = b - __bfloat162float(hb);
    return ((uint32_t)__bfloat16_as_ushort(__float2bfloat16(lb)) << 16) |
            (uint32_t)__bfloat16_as_ushort(__float2bfloat16(la));
}
// fp32 pair -> (hi bf16x2, lo bf16x2); identical rounding to pack_hi/pack_lo
__device__ __forceinline__ void split2(float2 p, uint32_t& hi, uint32_t& lo) {
    asm("cvt.rn.bf16x2.f32 %0, %1, %2;" : "=r"(hi) : "f"(p.y), "f"(p.x));
    float h0 = __uint_as_float(hi << 16);
    float h1 = __uint_as_float(hi & 0xffff0000u);
    float l0 = p.x - h0;
    float l1 = p.y - h1;
    asm("cvt.rn.bf16x2.f32 %0, %1, %2;" : "=r"(lo) : "f"(l1), "f"(l0));
}

// ---------------------------------------------------------------------------
// BIG-TILE projection GEMM (modes 0 and 3). 256x128 tile, 8 warps,
// 3-stage cp.async ring. R12: commit EVERY iteration (fixes last-stage
// under-wait race: empty groups keep CP_WAIT(1) honest).
// ---------------------------------------------------------------------------
template<int MODE>
__global__ __launch_bounds__(256)
void gemm_big(const __nv_bfloat16* __restrict__ Ahi_base,
              const __nv_bfloat16* __restrict__ Alo_base,
              const __nv_bfloat16* __restrict__ Bhi_base,
              const __nv_bfloat16* __restrict__ Blo_base,
              float* __restrict__ fout,
              __nv_bfloat16* __restrict__ ohi,
              __nv_bfloat16* __restrict__ olo,
              const float* __restrict__ bias) {
    constexpr int NSTAGE  = EMB / 32;           // 24
    constexpr int STAGES  = 3;
    constexpr int LDS     = 40;
    constexpr int A_BYTES = 256 * LDS * 2;      // 20480
    constexpr int B_BYTES = 128 * LDS * 2;      // 10240
    constexpr int STAGE_B = 2 * A_BYTES + 2 * B_BYTES;   // 61440

    extern __shared__ __align__(16) char dynsmem[];

    const int tid  = threadIdx.x;
    const int lane = tid & 31;
    const int wid  = tid >> 5;
    const int wm   = wid & 3;
    const int wn   = wid >> 2;
    const int l15  = lane & 15;
    const int bx = blockIdx.x, by = blockIdx.y;

    const __nv_bfloat16* Ah = Ahi_base + (long long)by * 256 * EMB;
    const __nv_bfloat16* Al = Alo_base + (long long)by * 256 * EMB;
    const __nv_bfloat16* Bh = Bhi_base + (long long)bx * 128 * EMB;
    const __nv_bfloat16* Bl = Blo_base + (long long)bx * 128 * EMB;

    const int arow = tid >> 2;
    const int acol = (tid & 3) * 8;

    const uint32_t sb = smem_u32(dynsmem);

    auto issue = [&](int s) {
        const uint32_t base = sb + (uint32_t)(s % STAGES) * STAGE_B;
        const long long k0 = (long long)s * 32;
        #pragma unroll
        for (int it = 0; it < 4; it++) {
            const int r = arow + it * 64;
            const uint32_t d = base + (uint32_t)(r * LDS + acol) * 2;
            cp16(d,           Ah + (long long)r * EMB + k0 + acol);
            cp16(d + A_BYTES, Al + (long long)r * EMB + k0 + acol);
        }
        #pragma unroll
        for (int it = 0; it < 2; it++) {
            const int r = arow + it * 64;
            const uint32_t d = base + 2 * A_BYTES + (uint32_t)(r * LDS + acol) * 2;
            cp16(d,           Bh + (long long)r * EMB + k0 + acol);
            cp16(d + B_BYTES, Bl + (long long)r * EMB + k0 + acol);
        }
    };

    float acc[4][8][4];
    #pragma unroll
    for (int i = 0; i < 4; i++)
        #pragma unroll
        for (int j = 0; j < 8; j++)
            #pragma unroll
            for (int e = 0; e < 4; e++) acc[i][j][e] = 0.f;

    issue(0); CP_COMMIT();
    issue(1); CP_COMMIT();

    for (int s = 0; s < NSTAGE; s++) {
        CP_WAIT(1);
        __syncthreads();
        if (s + 2 < NSTAGE) issue(s + 2);
        CP_COMMIT();                       // unconditional: keeps group count moving

        const uint32_t base = sb + (uint32_t)(s % STAGES) * STAGE_B;
        const uint32_t uAh = base;
        const uint32_t uAl = base + A_BYTES;
        const uint32_t uBh = base + 2 * A_BYTES;
        const uint32_t uBl = base + 2 * A_BYTES + B_BYTES;

        #pragma unroll
        for (int ks = 0; ks < 2; ks++) {
            uint32_t bh[8][2], bl[8][2];
            #pragma unroll
            for (int j = 0; j < 8; j++) {
                const int nr = wn * 64 + j * 8 + (l15 & 7);
                const int kc = ks * 16 + (l15 >> 3) * 8;
                const uint32_t off = (uint32_t)(nr * LDS + kc) * 2;
                ldsm_x2(bh[j], uBh + off);
                ldsm_x2(bl[j], uBl + off);
            }
            #pragma unroll
            for (int i = 0; i < 4; i++) {
                const int ar = wm * 64 + i * 16 + l15;
                const int ac = ks * 16 + (lane >> 4) * 8;
                const uint32_t aoff = (uint32_t)(ar * LDS + ac) * 2;
                uint32_t ah[4], al[4];
                ldsm_x4(ah, uAh + aoff);
                #pragma unroll
                for (int j = 0; j < 8; j++) mma_bf16(acc[i][j], ah, bh[j]);
                ldsm_x4(al, uAl + aoff);
                #pragma unroll
                for (int j = 0; j < 8; j++) mma_bf16(acc[i][j], ah, bl[j]);
                #pragma unroll
                for (int j = 0; j < 8; j++) mma_bf16(acc[i][j], al, bh[j]);
            }
        }
    }

    // ---- epilogue ----
    const int g = lane >> 2, t = lane & 3;
    #pragma unroll
    for (int i = 0; i < 4; i++) {
        const int m0 = by * 256 + wm * 64 + i * 16 + g;
        const int m1 = m0 + 8;
        #pragma unroll
        for (int j = 0; j < 8; j++) {
            const int n = bx * 128 + wn * 64 + j * 8 + 2 * t;
            const float c0 = acc[i][j][0], c1 = acc[i][j][1];
            const float c2 = acc[i][j][2], c3 = acc[i][j][3];
            if (MODE == 0) {
                long long o0 = (long long)m0 * QKVC + n;
                long long o1 = (long long)m1 * QKVC + n;
                *(uint32_t*)(ohi + o0) = pack_hi(c0, c1);
                *(uint32_t*)(olo + o0) = pack_lo(c0, c1);
                *(uint32_t*)(ohi + o1) = pack_hi(c2, c3);
                *(uint32_t*)(olo + o1) = pack_lo(c2, c3);
            } else {
                float2 w0 = { c0 + bias[n], c1 + bias[n + 1] };
                float2 w1 = { c2 + bias[n], c3 + bias[n + 1] };
                *(float2*)(fout + (long long)m0 * EMB + n) = w0;
                *(float2*)(fout + (long long)m1 * EMB + n) = w1;
            }
        }
    }
}

// ---------------------------------------------------------------------------
// Scores: Q,K bf16 hi/lo -> P = exp(s/8-20) fp32 UNNORMALIZED into attn
// region + psum partials. 128x64 tile, full-drain waits (CP_WAIT(0), safe).
// ---------------------------------------------------------------------------
__global__ __launch_bounds__(256, 2)
void score_gemm(const __nv_bfloat16* __restrict__ Qhi,
                const __nv_bfloat16* __restrict__ Qlo,
                float* __restrict__ psum,
                float* __restrict__ attn_un) {
    constexpr int NJ      = 2;
    constexpr int NSTAGE  = 2;       // K=64
    constexpr int STAGES  = 2;
    constexpr int LDS_A   = 40;
    constexpr int LDS_B   = 40;
    constexpr int A_BYTES = 128 * LDS_A * 2;
    constexpr int B_BYTES = 64 * LDS_B * 2;
    constexpr int STAGE_B = 2 * A_BYTES + 2 * B_BYTES;   // 30720

    extern __shared__ __align__(16) char dynsmem[];

    const int tid  = threadIdx.x;
    const int lane = tid & 31;
    const int wid  = tid >> 5;
    const int wm   = wid >> 2;
    const int wn   = wid & 3;
    const int l15  = lane & 15;
    const int bx = blockIdx.x, by = blockIdx.y, bz = blockIdx.z;
    const int bb = bz / NH, hh = bz % NH;

    long long ao = ((long long)bb * SEQL + by * 128) * QKVC + hh * HD;
    long long bo = ((long long)bb * SEQL + bx * 64) * QKVC + EMB + hh * HD;
    const __nv_bfloat16* Ah = Qhi + ao;
    const __nv_bfloat16* Al = Qlo + ao;
    const __nv_bfloat16* Bh = Qhi + bo;
    const __nv_bfloat16* Bl = Qlo + bo;

    const int arow0 = tid >> 2;
    const int acol  = (tid & 3) * 8;
    const int arow1 = arow0 + 64;

    const uint32_t sb = smem_u32(dynsmem);

    auto issue = [&](int s) {
        const uint32_t base = sb + (uint32_t)(s % STAGES) * STAGE_B;
        const long long k0 = (long long)s * 32;
        const uint32_t dA0 = base + (uint32_t)(arow0 * LDS_A + acol) * 2;
        const uint32_t dA1 = base + (uint32_t)(arow1 * LDS_A + acol) * 2;
        cp16(dA0,           Ah + (long long)arow0 * QKVC + k0 + acol);
        cp16(dA1,           Ah + (long long)arow1 * QKVC + k0 + acol);
        cp16(dA0 + A_BYTES, Al + (long long)arow0 * QKVC + k0 + acol);
        cp16(dA1 + A_BYTES, Al + (long long)arow1 * QKVC + k0 + acol);
        const uint32_t dB = base + 2 * A_BYTES + (uint32_t)(arow0 * LDS_B + acol) * 2;
        cp16(dB,           Bh + (long long)arow0 * QKVC + k0 + acol);
        cp16(dB + B_BYTES, Bl + (long long)arow0 * QKVC + k0 + acol);
    };

    float acc[4][NJ][4];
    #pragma unroll
    for (int i = 0; i < 4; i++)
        #pragma unroll
        for (int j = 0; j < NJ; j++)
            #pragma unroll
            for (int e = 0; e < 4; e++) acc[i][j][e] = 0.f;

    issue(0); CP_COMMIT();
    issue(1); CP_COMMIT();

    for (int s = 0; s < NSTAGE; s++) {
        CP_WAIT(0);                      // full drain: no race possible
        __syncthreads();

        const uint32_t base = sb + (uint32_t)(s % STAGES) * STAGE_B;
        const uint32_t uAh = base;
        const uint32_t uAl = base + A_BYTES;
        const uint32_t uBh = base + 2 * A_BYTES;
        const uint32_t uBl = base + 2 * A_BYTES + B_BYTES;

        #pragma unroll
        for (int ks = 0; ks < 2; ks++) {
            uint32_t bh[NJ][2], bl[NJ][2];
            #pragma unroll
            for (int j = 0; j < NJ; j++) {
                const int nr = wn * 16 + j * 8 + (l15 & 7);
                const int kc = ks * 16 + (l15 >> 3) * 8;
                const uint32_t off = (uint32_t)(nr * LDS_B + kc) * 2;
                ldsm_x2(bh[j], uBh + off);
                ldsm_x2(bl[j], uBl + off);
            }
            #pragma unroll
            for (int i = 0; i < 4; i++) {
                const int ar = wm * 64 + i * 16 + l15;
                const int ac = ks * 16 + (lane >> 4) * 8;
                const uint32_t aoff = (uint32_t)(ar * LDS_A + ac) * 2;
                uint32_t ah[4], al[4];
                ldsm_x4(ah, uAh + aoff);
                #pragma unroll
                for (int j = 0; j < NJ; j++) mma_bf16(acc[i][j], ah, bh[j]);
                ldsm_x4(al, uAl + aoff);
                #pragma unroll
                for (int j = 0; j < NJ; j++) mma_bf16(acc[i][j], ah, bl[j]);
                #pragma unroll
                for (int j = 0; j < NJ; j++) mma_bf16(acc[i][j], al, bh[j]);
            }
        }
        __syncthreads();
    }

    // ---- epilogue: exp, psum, fp32 tile stage -> coalesced store ----
    float* sO = (float*)dynsmem;   // [128][66] fp32 = 33792 B
    const int g = lane >> 2, t = lane & 3;
    #pragma unroll
    for (int i = 0; i < 4; i++) {
        const int r0 = wm * 64 + i * 16 + g;
        const int r1 = r0 + 8;
        const int m0 = by * 128 + r0;
        const int m1 = by * 128 + r1;
        float s0 = 0.f, s1 = 0.f;
        #pragma unroll
        for (int j = 0; j < NJ; j++) {
            float v0 = __expf(fmaf(acc[i][j][0], K_SCALE, -EXP_OFF));
            float v1 = __expf(fmaf(acc[i][j][1], K_SCALE, -EXP_OFF));
            float v2 = __expf(fmaf(acc[i][j][2], K_SCALE, -EXP_OFF));
            float v3 = __expf(fmaf(acc[i][j][3], K_SCALE, -EXP_OFF));
            s0 += v0 + v1; s1 += v2 + v3;
            const int nloc = wn * 16 + j * 8 + 2 * t;
            float2 a01 = { v0, v1 }, a23 = { v2, v3 };
            *(float2*)(sO + r0 * 66 + nloc) = a01;
            *(float2*)(sO + r1 * 66 + nloc) = a23;
        }
        s0 += __shfl_xor_sync(0xffffffffu, s0, 1);
        s0 += __shfl_xor_sync(0xffffffffu, s0, 2);
        s1 += __shfl_xor_sync(0xffffffffu, s1, 1);
        s1 += __shfl_xor_sync(0xffffffffu, s1, 2);
        if (t == 0) {
            psum[((long long)bz * SEQL + m0) * 64 + bx * 4 + wn] = s0;
            psum[((long long)bz * SEQL + m1) * 64 + bx * 4 + wn] = s1;
        }
    }
    __syncthreads();

    // coalesced copy-out: 128 rows x 32 float2
    float* abase = attn_un + ((long long)bz * SEQL + by * 128) * SEQL + bx * 64;
    #pragma unroll
    for (int k = 0; k < 16; k++) {
        const int idx = tid + k * 256;
        const int row = idx >> 5;
        const int w2  = idx & 31;
        float2 v = *(const float2*)(sO + row * 66 + w2 * 2);
        *(float2*)(abase + (long long)row * SEQL + w2 * 2) = v;
    }
}

// ---------------------------------------------------------------------------
// PV: P read as fp32 from attn buffer, split to bf16 hi/lo in-register.
// Normalized attn written in place. R12: unconditional CP_COMMIT per iter
// (fixes the last-stage under-wait that corrupted cols 992..1023) and a
// CP_WAIT(0) before the epilogue reuses the pipeline smem.
// ---------------------------------------------------------------------------
#define STG_LDS 66

__global__ __launch_bounds__(256, 2)
void pv_gemm(const float* __restrict__ Pfp,       // attn region (unnormalized)
             float* attn,                          // same region (write norm)
             const __nv_bfloat16* __restrict__ Vhi,
             const __nv_bfloat16* __restrict__ Vlo,
             __nv_bfloat16* __restrict__ ohi,
             __nv_bfloat16* __restrict__ olo,
             const float* __restrict__ inv) {
    constexpr int NJ      = 2;
    constexpr int NSTAGE  = 32;      // K=1024
    constexpr int STAGES  = 3;
    constexpr int LDSP    = 36;                       // fp32 words per row
    constexpr int A_BYTES = 128 * LDSP * 4;           // 18432
    constexpr int LDS_B   = 72;
    constexpr int B_BYTES = 32 * LDS_B * 2;           // 4608
    constexpr int STAGE_B = A_BYTES + 2 * B_BYTES;    // 27648

    extern __shared__ __align__(16) char dynsmem[];

    const int tid  = threadIdx.x;
    const int lane = tid & 31;
    const int wid  = tid >> 5;
    const int wm   = wid >> 2;
    const int wn   = wid & 3;
    const int l15  = lane & 15;
    const int g    = lane >> 2;
    const int t    = lane & 3;
    const int by = blockIdx.y, bz = blockIdx.z;
    const int bb = bz / NH, hh = bz % NH;

    const float* Ptile = Pfp + (long long)bz * SEQL * SEQL + (long long)by * 128 * SEQL;
    float* attn_tile   = attn + (long long)bz * SEQL * SEQL + (long long)by * 128 * SEQL;
    const long long auxbase = (long long)bz * SEQL + by * 128;

    const int brow2 = tid >> 3;
    const int bcol2 = (tid & 7) * 8;

    const uint32_t sb = smem_u32(dynsmem);

    auto issue = [&](int s) {
        const uint32_t base = sb + (uint32_t)(s % STAGES) * STAGE_B;
        const long long k0 = (long long)s * 32;
        #pragma unroll
        for (int it = 0; it < 4; it++) {
            const int idx = tid + it * 256;
            const int row = idx >> 3, c16 = idx & 7;
            cp16(base + (uint32_t)(row * LDSP * 4 + c16 * 16),
                 Ptile + (long long)row * SEQL + k0 + c16 * 4);
        }
        long long vo = ((long long)bb * SEQL + s * 32 + brow2) * QKVC
                     + 2 * EMB + hh * HD + bcol2;
        const uint32_t dB = base + A_BYTES + (uint32_t)(brow2 * LDS_B + bcol2) * 2;
        cp16(dB,           Vhi + vo);
        cp16(dB + B_BYTES, Vlo + vo);
    };

    float acc[4][NJ][4];
    #pragma unroll
    for (int i = 0; i < 4; i++)
        #pragma unroll
        for (int j = 0; j < NJ; j++)
            #pragma unroll
            for (int e = 0; e < 4; e++) acc[i][j][e] = 0.f;

    issue(0); CP_COMMIT();
    issue(1); CP_COMMIT();

    for (int s = 0; s < NSTAGE; s++) {
        CP_WAIT(1);
        __syncthreads();
        if (s + 2 < NSTAGE) issue(s + 2);
        CP_COMMIT();                      // unconditional: last stages drain properly

        const int slot = s % STAGES;
        const float* sA = (const float*)(dynsmem + slot * STAGE_B);
        const uint32_t base = sb + (uint32_t)slot * STAGE_B;
        const uint32_t uBh = base + A_BYTES;
        const uint32_t uBl = base + A_BYTES + B_BYTES;

        // normalized attn write (in place; cols s*32.. never re-read later)
        #pragma unroll
        for (int k = 0; k < 8; k++) {
            const int idx = tid + k * 256;
            const int row = idx >> 4;
            const int c2  = idx & 15;
            float2 v = *(const float2*)(sA + row * LDSP + c2 * 2);
            const float iv = inv[auxbase + row];
            float2 w = { v.x * iv, v.y * iv };
            *(float2*)(attn_tile + (long long)row * SEQL + s * 32 + c2 * 2) = w;
        }

        #pragma unroll
        for (int ks = 0; ks < 2; ks++) {
            uint32_t bh[NJ][2], bl[NJ][2];
            #pragma unroll
            for (int j = 0; j < NJ; j++) {
                const int kr = ks * 16 + l15;
                const int nc = wn * 16 + j * 8;
                const uint32_t off = (uint32_t)(kr * LDS_B + nc) * 2;
                ldsm_x2t(bh[j], uBh + off);
                ldsm_x2t(bl[j], uBl + off);
            }
            #pragma unroll
            for (int i = 0; i < 4; i++) {
                const int r0 = wm * 64 + i * 16 + g;
                const int c0 = ks * 16 + 2 * t;
                float2 q00 = *(const float2*)(sA + r0 * LDSP + c0);
                float2 q10 = *(const float2*)(sA + (r0 + 8) * LDSP + c0);
                float2 q01 = *(const float2*)(sA + r0 * LDSP + c0 + 8);
                float2 q11 = *(const float2*)(sA + (r0 + 8) * LDSP + c0 + 8);
                uint32_t ah[4], al[4];
                split2(q00, ah[0], al[0]);
                split2(q10, ah[1], al[1]);
                split2(q01, ah[2], al[2]);
                split2(q11, ah[3], al[3]);
                #pragma unroll
                for (int j = 0; j < NJ; j++) mma_bf16(acc[i][j], ah, bh[j]);
                #pragma unroll
                for (int j = 0; j < NJ; j++) mma_bf16(acc[i][j], ah, bl[j]);
                #pragma unroll
                for (int j = 0; j < NJ; j++) mma_bf16(acc[i][j], al, bh[j]);
            }
        }
    }

    // ---- epilogue: drain async, then reuse smem for staged coalesced store
    CP_WAIT(0);
    __syncthreads();
    __nv_bfloat16* sOh = (__nv_bfloat16*)dynsmem;        // [128][66]
    __nv_bfloat16* sOl = sOh + 128 * STG_LDS;

    #pragma unroll
    for (int i = 0; i < 4; i++) {
        const int r0 = wm * 64 + i * 16 + g;
        const int r1 = r0 + 8;
        const float inv0 = inv[auxbase + r0];
        const float inv1 = inv[auxbase + r1];
        #pragma unroll
        for (int j = 0; j < NJ; j++) {
            float v0 = acc[i][j][0] * inv0, v1 = acc[i][j][1] * inv0;
            float v2 = acc[i][j][2] * inv1, v3 = acc[i][j][3] * inv1;
            const int nloc = wn * 16 + j * 8 + 2 * t;
            *(uint32_t*)(sOh + r0 * STG_LDS + nloc) = pack_hi(v0, v1);
            *(uint32_t*)(sOl + r0 * STG_LDS + nloc) = pack_lo(v0, v1);
            *(uint32_t*)(sOh + r1 * STG_LDS + nloc) = pack_hi(v2, v3);
            *(uint32_t*)(sOl + r1 * STG_LDS + nloc) = pack_lo(v2, v3);
        }
    }
    __syncthreads();

    #pragma unroll
    for (int k = 0; k < 16; k++) {
        const int idx  = tid + k * 256;
        const int row  = idx >> 5;
        const int word = idx & 31;
        const uint32_t wh = *(const uint32_t*)(sOh + row * STG_LDS + word * 2);
        const uint32_t wl = *(const uint32_t*)(sOl + row * STG_LDS + word * 2);
        long long go = (((long long)bb * SEQL + by * 128 + row) * EMB + hh * HD) + word * 2;
        *(uint32_t*)(ohi + go) = wh;
        *(uint32_t*)(olo + go) = wl;
    }
}

// ---------------------------------------------------------------------------
// fp32 -> bf16 hi/lo split
// ---------------------------------------------------------------------------
__global__ void split_hilo(const float* __restrict__ src,
                           __nv_bfloat16* __restrict__ hi,
                           __nv_bfloat16* __restrict__ lo, int n) {
    int i = blockIdx.x * 256 + threadIdx.x;
    if (i < n) {
        float v = src[i];
        __nv_bfloat16 h = __float2bfloat16(v);
        hi[i] = h;
        lo[i] = __float2bfloat16(v - __bfloat162float(h));
    }
}

// 64 partials per row -> 1/sum
__global__ void inv_rows(const float* __restrict__ psum, float* __restrict__ inv) {
    int r = blockIdx.x * 256 + threadIdx.x;
    if (r < AROWS) {
        float s = 0.f;
        #pragma unroll
        for (int j = 0; j < 64; j++) s += psum[(long long)r * 64 + j];
        inv[r] = 1.0f / s;
    }
}

// ---------------------------------------------------------------------------
// Launch
// ---------------------------------------------------------------------------
extern "C" void kernel_launch(void* const* d_in, const int* in_sizes, int n_in,
                              void* d_out, int out_size) {
    (void)in_sizes; (void)n_in; (void)out_size;
    const float* x      = (const float*)d_in[0];
    const float* w_qkv  = (const float*)d_in[1];
    const float* w_proj = (const float*)d_in[2];
    const float* b_proj = (const float*)d_in[3];

    float* out  = (float*)d_out;
    float* attn = out + (long long)ROWS * EMB;

    __nv_bfloat16 *xh, *xl, *wqh, *wql, *wph, *wpl, *qh, *ql, *ohh, *ohl;
    float *psum, *inv;
    cudaGetSymbolAddress((void**)&xh,  g_x_hi);    cudaGetSymbolAddress((void**)&xl,  g_x_lo);
    cudaGetSymbolAddress((void**)&wqh, g_wqkv_hi); cudaGetSymbolAddress((void**)&wql, g_wqkv_lo);
    cudaGetSymbolAddress((void**)&wph, g_wp_hi);   cudaGetSymbolAddress((void**)&wpl, g_wp_lo);
    cudaGetSymbolAddress((void**)&qh,  g_qkv_hi);  cudaGetSymbolAddress((void**)&ql,  g_qkv_lo);
    cudaGetSymbolAddress((void**)&ohh, g_oh_hi);   cudaGetSymbolAddress((void**)&ohl, g_oh_lo);
    cudaGetSymbolAddress((void**)&psum, g_psum);   cudaGetSymbolAddress((void**)&inv,  g_inv);

    constexpr int SMBIG = 3 * 61440;  // 184320
    constexpr int SM1   = 2 * 30720;  //  61440  (>= fp32 staging 33792)
    constexpr int SM2   = 3 * 27648;  //  82944  (>= hi/lo staging 33792)
    static bool attr_done = false;
    if (!attr_done) {
        cudaFuncSetAttribute(gemm_big<0>, cudaFuncAttributeMaxDynamicSharedMemorySize, SMBIG);
        cudaFuncSetAttribute(gemm_big<3>, cudaFuncAttributeMaxDynamicSharedMemorySize, SMBIG);
        cudaFuncSetAttribute(score_gemm, cudaFuncAttributeMaxDynamicSharedMemorySize, SM1);
        cudaFuncSetAttribute(pv_gemm,    cudaFuncAttributeMaxDynamicSharedMemorySize, SM2);
        attr_done = true;
    }

    // 0) hi/lo splits of fp32 inputs
    split_hilo<<<(ROWS*EMB + 255)/256, 256>>>(x, xh, xl, ROWS*EMB);
    split_hilo<<<(QKVC*EMB + 255)/256, 256>>>(w_qkv, wqh, wql, QKVC*EMB);
    split_hilo<<<(EMB*EMB + 255)/256, 256>>>(w_proj, wph, wpl, EMB*EMB);

    // 1) QKV projection -> qkv hi/lo
    gemm_big<0><<<dim3(QKVC/128, ROWS/256), 256, SMBIG>>>(
        xh, xl, wqh, wql, nullptr, qh, ql, nullptr);

    // 2) Scores + exp -> UNNORMALIZED fp32 P in attn region + psum
    score_gemm<<<dim3(16, 8, ZTOT), 256, SM1>>>(qh, ql, psum, attn);

    // 3) 1/rowsum
    inv_rows<<<(AROWS + 255)/256, 256>>>(psum, inv);

    // 4) PV: read fp32 P, split in-register, MMA; normalize attn in place; oh
    pv_gemm<<<dim3(1, 8, ZTOT), 256, SM2>>>(attn, attn, qh, ql, ohh, ohl, inv);

    // 5) Output projection + bias -> fp32 out
    gemm_big<3><<<dim3(EMB/128, ROWS/256), 256, SMBIG>>>(
        ohh, ohl, wph, wpl, out, nullptr, nullptr, b_proj);
}

// round 13
// speedup vs baseline: 1.0149x; 1.0149x over previous
#include <cuda_runtime.h>
#include <cuda_bf16.h>
#include <cstdint>

// ---------------------------------------------------------------------------
// Problem constants
// ---------------------------------------------------------------------------
#define BATCHN  8
#define SEQL    1024
#define EMB     768
#define NH      12
#define HD      64
#define ROWS    (BATCHN*SEQL)        // 8192
#define QKVC    (3*EMB)              // 2304
#define ZTOT    (BATCHN*NH)          // 96
#define AROWS   (ZTOT*SEQL)          // 98304
#define K_SCALE 0.125f
#define EXP_OFF 20.0f

// ---------------------------------------------------------------------------
// Device scratch (static globals; allocation-free)
// ---------------------------------------------------------------------------
__device__ __align__(16) __nv_bfloat16 g_x_hi  [ROWS*EMB];
__device__ __align__(16) __nv_bfloat16 g_x_lo  [ROWS*EMB];
__device__ __align__(16) __nv_bfloat16 g_wqkv_hi[QKVC*EMB];
__device__ __align__(16) __nv_bfloat16 g_wqkv_lo[QKVC*EMB];
__device__ __align__(16) __nv_bfloat16 g_wp_hi [EMB*EMB];
__device__ __align__(16) __nv_bfloat16 g_wp_lo [EMB*EMB];
__device__ __align__(16) __nv_bfloat16 g_qkv_hi[(size_t)ROWS*QKVC];
__device__ __align__(16) __nv_bfloat16 g_qkv_lo[(size_t)ROWS*QKVC];
__device__ __align__(16) __nv_bfloat16 g_p_hi  [(size_t)ZTOT*SEQL*SEQL];
__device__ __align__(16) __nv_bfloat16 g_p_lo  [(size_t)ZTOT*SEQL*SEQL];
__device__ __align__(16) __nv_bfloat16 g_oh_hi [ROWS*EMB];
__device__ __align__(16) __nv_bfloat16 g_oh_lo [ROWS*EMB];
__device__ float g_psum[(size_t)AROWS*64];
__device__ float g_inv [AROWS];

// ---------------------------------------------------------------------------
// PTX helpers (all sm_80-era: safe on plain compute_103)
// ---------------------------------------------------------------------------
__device__ __forceinline__ uint32_t smem_u32(const void* p) {
    uint32_t a;
    asm("{ .reg .u64 t; cvta.to.shared.u64 t, %1; cvt.u32.u64 %0, t; }"
        : "=r"(a) : "l"(p));
    return a;
}
__device__ __forceinline__ void cp16(uint32_t dst, const void* src) {
    asm volatile("cp.async.cg.shared.global [%0], [%1], 16;"
                 :: "r"(dst), "l"(src));
}
#define CP_COMMIT() asm volatile("cp.async.commit_group;" ::: "memory")
#define CP_WAIT(n)  asm volatile("cp.async.wait_group %0;" :: "n"(n) : "memory")

__device__ __forceinline__ void ldsm_x4(uint32_t* r, uint32_t addr) {
    asm volatile("ldmatrix.sync.aligned.m8n8.x4.shared.b16 {%0,%1,%2,%3}, [%4];"
        : "=r"(r[0]), "=r"(r[1]), "=r"(r[2]), "=r"(r[3]) : "r"(addr));
}
__device__ __forceinline__ void ldsm_x2(uint32_t* r, uint32_t addr) {
    asm volatile("ldmatrix.sync.aligned.m8n8.x2.shared.b16 {%0,%1}, [%2];"
        : "=r"(r[0]), "=r"(r[1]) : "r"(addr));
}
__device__ __forceinline__ void ldsm_x2t(uint32_t* r, uint32_t addr) {
    asm volatile("ldmatrix.sync.aligned.m8n8.x2.trans.shared.b16 {%0,%1}, [%2];"
        : "=r"(r[0]), "=r"(r[1]) : "r"(addr));
}
__device__ __forceinline__ void mma_bf16(float* c, const uint32_t* a, const uint32_t* b) {
    asm volatile("mma.sync.aligned.m16n8k16.row.col.f32.bf16.bf16.f32 "
        "{%0,%1,%2,%3}, {%4,%5,%6,%7}, {%8,%9}, {%0,%1,%2,%3};"
        : "+f"(c[0]), "+f"(c[1]), "+f"(c[2]), "+f"(c[3])
        : "r"(a[0]), "r"(a[1]), "r"(a[2]), "r"(a[3]), "r"(b[0]), "r"(b[1]));
}

__device__ __forceinline__ uint32_t pack_hi(float a, float b) {
    return ((uint32_t)__bfloat16_as_ushort(__float2bfloat16(b)) << 16) |
            (uint32_t)__bfloat16_as_ushort(__float2bfloat16(a));
}
__device__ __forceinline__ uint32_t pack_lo(float a, float b) {
    __nv_bfloat16 ha = __float2bfloat16(a), hb = __float2bfloat16(b);
    float la = a - __bfloat162float(ha), lb = b - __bfloat162float(hb);
    return ((uint32_t)__bfloat16_as_ushort(__float2bfloat16(lb)) << 16) |
            (uint32_t)__bfloat16_as_ushort(__float2bfloat16(la));
}

// ---------------------------------------------------------------------------
// BIG-TILE projection GEMM (modes 0 and 3). 256x128 tile, 8 warps,
// 3-stage cp.async ring, unconditional commit (R12 race fix). by0 = row
// block offset for batch-split streaming.
// ---------------------------------------------------------------------------
template<int MODE>
__global__ __launch_bounds__(256)
void gemm_big(const __nv_bfloat16* __restrict__ Ahi_base,
              const __nv_bfloat16* __restrict__ Alo_base,
              const __nv_bfloat16* __restrict__ Bhi_base,
              const __nv_bfloat16* __restrict__ Blo_base,
              float* __restrict__ fout,
              __nv_bfloat16* __restrict__ ohi,
              __nv_bfloat16* __restrict__ olo,
              const float* __restrict__ bias,
              int by0) {
    constexpr int NSTAGE  = EMB / 32;           // 24
    constexpr int STAGES  = 3;
    constexpr int LDS     = 40;
    constexpr int A_BYTES = 256 * LDS * 2;      // 20480
    constexpr int B_BYTES = 128 * LDS * 2;      // 10240
    constexpr int STAGE_B = 2 * A_BYTES + 2 * B_BYTES;   // 61440

    extern __shared__ __align__(16) char dynsmem[];

    const int tid  = threadIdx.x;
    const int lane = tid & 31;
    const int wid  = tid >> 5;
    const int wm   = wid & 3;
    const int wn   = wid >> 2;
    const int l15  = lane & 15;
    const int bx = blockIdx.x, by = blockIdx.y + by0;

    const __nv_bfloat16* Ah = Ahi_base + (long long)by * 256 * EMB;
    const __nv_bfloat16* Al = Alo_base + (long long)by * 256 * EMB;
    const __nv_bfloat16* Bh = Bhi_base + (long long)bx * 128 * EMB;
    const __nv_bfloat16* Bl = Blo_base + (long long)bx * 128 * EMB;

    const int arow = tid >> 2;
    const int acol = (tid & 3) * 8;

    const uint32_t sb = smem_u32(dynsmem);

    auto issue = [&](int s) {
        const uint32_t base = sb + (uint32_t)(s % STAGES) * STAGE_B;
        const long long k0 = (long long)s * 32;
        #pragma unroll
        for (int it = 0; it < 4; it++) {
            const int r = arow + it * 64;
            const uint32_t d = base + (uint32_t)(r * LDS + acol) * 2;
            cp16(d,           Ah + (long long)r * EMB + k0 + acol);
            cp16(d + A_BYTES, Al + (long long)r * EMB + k0 + acol);
        }
        #pragma unroll
        for (int it = 0; it < 2; it++) {
            const int r = arow + it * 64;
            const uint32_t d = base + 2 * A_BYTES + (uint32_t)(r * LDS + acol) * 2;
            cp16(d,           Bh + (long long)r * EMB + k0 + acol);
            cp16(d + B_BYTES, Bl + (long long)r * EMB + k0 + acol);
        }
    };

    float acc[4][8][4];
    #pragma unroll
    for (int i = 0; i < 4; i++)
        #pragma unroll
        for (int j = 0; j < 8; j++)
            #pragma unroll
            for (int e = 0; e < 4; e++) acc[i][j][e] = 0.f;

    issue(0); CP_COMMIT();
    issue(1); CP_COMMIT();

    for (int s = 0; s < NSTAGE; s++) {
        CP_WAIT(1);
        __syncthreads();
        if (s + 2 < NSTAGE) issue(s + 2);
        CP_COMMIT();                      // unconditional: drains correctly at tail

        const uint32_t base = sb + (uint32_t)(s % STAGES) * STAGE_B;
        const uint32_t uAh = base;
        const uint32_t uAl = base + A_BYTES;
        const uint32_t uBh = base + 2 * A_BYTES;
        const uint32_t uBl = base + 2 * A_BYTES + B_BYTES;

        #pragma unroll
        for (int ks = 0; ks < 2; ks++) {
            uint32_t bh[8][2], bl[8][2];
            #pragma unroll
            for (int j = 0; j < 8; j++) {
                const int nr = wn * 64 + j * 8 + (l15 & 7);
                const int kc = ks * 16 + (l15 >> 3) * 8;
                const uint32_t off = (uint32_t)(nr * LDS + kc) * 2;
                ldsm_x2(bh[j], uBh + off);
                ldsm_x2(bl[j], uBl + off);
            }
            #pragma unroll
            for (int i = 0; i < 4; i++) {
                const int ar = wm * 64 + i * 16 + l15;
                const int ac = ks * 16 + (lane >> 4) * 8;
                const uint32_t aoff = (uint32_t)(ar * LDS + ac) * 2;
                uint32_t ah[4], al[4];
                ldsm_x4(ah, uAh + aoff);
                #pragma unroll
                for (int j = 0; j < 8; j++) mma_bf16(acc[i][j], ah, bh[j]);
                ldsm_x4(al, uAl + aoff);
                #pragma unroll
                for (int j = 0; j < 8; j++) mma_bf16(acc[i][j], ah, bl[j]);
                #pragma unroll
                for (int j = 0; j < 8; j++) mma_bf16(acc[i][j], al, bh[j]);
            }
        }
    }

    // ---- epilogue ----
    const int g = lane >> 2, t = lane & 3;
    #pragma unroll
    for (int i = 0; i < 4; i++) {
        const int m0 = by * 256 + wm * 64 + i * 16 + g;
        const int m1 = m0 + 8;
        #pragma unroll
        for (int j = 0; j < 8; j++) {
            const int n = bx * 128 + wn * 64 + j * 8 + 2 * t;
            const float c0 = acc[i][j][0], c1 = acc[i][j][1];
            const float c2 = acc[i][j][2], c3 = acc[i][j][3];
            if (MODE == 0) {
                long long o0 = (long long)m0 * QKVC + n;
                long long o1 = (long long)m1 * QKVC + n;
                *(uint32_t*)(ohi + o0) = pack_hi(c0, c1);
                *(uint32_t*)(olo + o0) = pack_lo(c0, c1);
                *(uint32_t*)(ohi + o1) = pack_hi(c2, c3);
                *(uint32_t*)(olo + o1) = pack_lo(c2, c3);
            } else {
                float2 w0 = { c0 + bias[n], c1 + bias[n + 1] };
                float2 w1 = { c2 + bias[n], c3 + bias[n + 1] };
                *(float2*)(fout + (long long)m0 * EMB + n) = w0;
                *(float2*)(fout + (long long)m1 * EMB + n) = w1;
            }
        }
    }
}

// ---------------------------------------------------------------------------
// Attention kernels (modes 1 and 2), 128x64 tile, 2 CTAs/SM, staged
// coalesced epilogues (R10, best known). z0 = head-batch offset.
// ---------------------------------------------------------------------------
#define STG_LDS 66

template<int MODE>
__global__ __launch_bounds__(256, 2)
void mma_gemm(const __nv_bfloat16* __restrict__ Ahi_base,
              const __nv_bfloat16* __restrict__ Alo_base,
              const __nv_bfloat16* __restrict__ Bhi_base,
              const __nv_bfloat16* __restrict__ Blo_base,
              float* __restrict__ fout,
              __nv_bfloat16* __restrict__ ohi,
              __nv_bfloat16* __restrict__ olo,
              const float* __restrict__ aux,
              int z0) {
    constexpr int NJ      = 2;
    constexpr int KTOT    = (MODE == 1) ? 64 : 1024;
    constexpr int NSTAGE  = KTOT / 32;
    constexpr int STAGES  = (MODE == 1) ? 2 : 3;
    constexpr int LDS_A   = 40;
    constexpr int LDS_B   = (MODE == 2) ? 72 : 40;
    constexpr int A_BYTES = 128 * LDS_A * 2;
    constexpr int B_BYTES = (MODE == 2) ? 32 * LDS_B * 2 : 64 * LDS_B * 2;
    constexpr int STAGE_B = 2 * A_BYTES + 2 * B_BYTES;

    extern __shared__ __align__(16) char dynsmem[];

    const int tid  = threadIdx.x;
    const int lane = tid & 31;
    const int wid  = tid >> 5;
    const int wm   = wid >> 2;
    const int wn   = wid & 3;
    const int l15  = lane & 15;
    const int bx = blockIdx.x, by = blockIdx.y, bz = blockIdx.z + z0;
    const int bb = bz / NH, hh = bz % NH;

    const __nv_bfloat16 *Ah, *Al, *Bh, *Bl;
    long long LDA = 0, LDB = 0;
    if (MODE == 1) {
        LDA = QKVC; LDB = QKVC;
        long long ao = ((long long)bb * SEQL + by * 128) * QKVC + hh * HD;
        long long bo = ((long long)bb * SEQL + bx * 64) * QKVC + EMB + hh * HD;
        Ah = Ahi_base + ao; Al = Alo_base + ao;
        Bh = Bhi_base + bo; Bl = Blo_base + bo;
    } else {
        LDA = SEQL; LDB = QKVC;
        long long ao = (long long)bz * SEQL * SEQL + (long long)by * 128 * SEQL;
        Ah = Ahi_base + ao; Al = Alo_base + ao;
        Bh = Bhi_base;      Bl = Blo_base;
    }
    float* attn_tile = nullptr;
    if (MODE == 2)
        attn_tile = fout + (long long)bz * SEQL * SEQL + (long long)by * 128 * SEQL;
    const long long auxbase = (MODE == 2) ? ((long long)bz * SEQL + by * 128) : 0;

    const int arow0 = tid >> 2;
    const int acol  = (tid & 3) * 8;
    const int arow1 = arow0 + 64;
    const int brow2 = tid >> 3;
    const int bcol2 = (tid & 7) * 8;

    const uint32_t sb = smem_u32(dynsmem);

    auto issue = [&](int s) {
        const uint32_t base = sb + (uint32_t)(s % STAGES) * STAGE_B;
        const long long k0 = (long long)s * 32;
        const uint32_t dA0 = base + (uint32_t)(arow0 * LDS_A + acol) * 2;
        const uint32_t dA1 = base + (uint32_t)(arow1 * LDS_A + acol) * 2;
        cp16(dA0,           Ah + (long long)arow0 * LDA + k0 + acol);
        cp16(dA1,           Ah + (long long)arow1 * LDA + k0 + acol);
        cp16(dA0 + A_BYTES, Al + (long long)arow0 * LDA + k0 + acol);
        cp16(dA1 + A_BYTES, Al + (long long)arow1 * LDA + k0 + acol);
        if (MODE != 2) {
            const uint32_t dB = base + 2 * A_BYTES + (uint32_t)(arow0 * LDS_B + acol) * 2;
            cp16(dB,           Bh + (long long)arow0 * LDB + k0 + acol);
            cp16(dB + B_BYTES, Bl + (long long)arow0 * LDB + k0 + acol);
        } else {
            long long vo = ((long long)bb * SEQL + s * 32 + brow2) * QKVC
                         + 2 * EMB + hh * HD + bcol2;
            const uint32_t dB = base + 2 * A_BYTES + (uint32_t)(brow2 * LDS_B + bcol2) * 2;
            cp16(dB,           Bh + vo);
            cp16(dB + B_BYTES, Bl + vo);
        }
    };

    float acc[4][NJ][4];
    #pragma unroll
    for (int i = 0; i < 4; i++)
        #pragma unroll
        for (int j = 0; j < NJ; j++)
            #pragma unroll
            for (int e = 0; e < 4; e++) acc[i][j][e] = 0.f;

    #pragma unroll
    for (int p = 0; p < STAGES - 1 && p < NSTAGE; p++) { issue(p); CP_COMMIT(); }

    for (int s = 0; s < NSTAGE; s++) {
        CP_WAIT(STAGES - 2);
        __syncthreads();
        if (s + STAGES - 1 < NSTAGE) issue(s + STAGES - 1);
        CP_COMMIT();                      // unconditional: drains correctly at tail

        const int slot = s % STAGES;
        const uint32_t base = sb + (uint32_t)slot * STAGE_B;

        if (MODE == 2) {
            #pragma unroll
            for (int cch = 0; cch < 2; cch++) {
                const int r = (cch == 0) ? arow0 : arow1;
                const char* sp = dynsmem + slot * STAGE_B + (r * LDS_A + acol) * 2;
                uint4 vh = *(const uint4*)sp;
                uint4 vl = *(const uint4*)(sp + A_BYTES);
                const __nv_bfloat16* eh = (const __nv_bfloat16*)&vh;
                const __nv_bfloat16* el = (const __nv_bfloat16*)&vl;
                const float iv = aux[auxbase + r];
                long long ab = (long long)r * SEQL + s * 32 + acol;
                float4 o0, o1;
                o0.x = (__bfloat162float(eh[0]) + __bfloat162float(el[0])) * iv;
                o0.y = (__bfloat162float(eh[1]) + __bfloat162float(el[1])) * iv;
                o0.z = (__bfloat162float(eh[2]) + __bfloat162float(el[2])) * iv;
                o0.w = (__bfloat162float(eh[3]) + __bfloat162float(el[3])) * iv;
                o1.x = (__bfloat162float(eh[4]) + __bfloat162float(el[4])) * iv;
                o1.y = (__bfloat162float(eh[5]) + __bfloat162float(el[5])) * iv;
                o1.z = (__bfloat162float(eh[6]) + __bfloat162float(el[6])) * iv;
                o1.w = (__bfloat162float(eh[7]) + __bfloat162float(el[7])) * iv;
                *(float4*)(attn_tile + ab)     = o0;
                *(float4*)(attn_tile + ab + 4) = o1;
            }
        }

        const uint32_t uAh = base;
        const uint32_t uAl = base + A_BYTES;
        const uint32_t uBh = base + 2 * A_BYTES;
        const uint32_t uBl = base + 2 * A_BYTES + B_BYTES;

        #pragma unroll
        for (int ks = 0; ks < 2; ks++) {
            uint32_t bh[NJ][2], bl[NJ][2];
            #pragma unroll
            for (int j = 0; j < NJ; j++) {
                if (MODE == 2) {
                    const int kr = ks * 16 + l15;
                    const int nc = wn * 16 + j * 8;
                    const uint32_t off = (uint32_t)(kr * LDS_B + nc) * 2;
                    ldsm_x2t(bh[j], uBh + off);
                    ldsm_x2t(bl[j], uBl + off);
                } else {
                    const int nr = wn * 16 + j * 8 + (l15 & 7);
                    const int kc = ks * 16 + (l15 >> 3) * 8;
                    const uint32_t off = (uint32_t)(nr * LDS_B + kc) * 2;
                    ldsm_x2(bh[j], uBh + off);
                    ldsm_x2(bl[j], uBl + off);
                }
            }
            #pragma unroll
            for (int i = 0; i < 4; i++) {
                const int ar = wm * 64 + i * 16 + l15;
                const int ac = ks * 16 + (lane >> 4) * 8;
                const uint32_t aoff = (uint32_t)(ar * LDS_A + ac) * 2;
                uint32_t ah[4], al[4];
                ldsm_x4(ah, uAh + aoff);
                #pragma unroll
                for (int j = 0; j < NJ; j++) mma_bf16(acc[i][j], ah, bh[j]);
                ldsm_x4(al, uAl + aoff);
                #pragma unroll
                for (int j = 0; j < NJ; j++) mma_bf16(acc[i][j], ah, bl[j]);
                #pragma unroll
                for (int j = 0; j < NJ; j++) mma_bf16(acc[i][j], al, bh[j]);
            }
        }
        __syncthreads();
    }

    // ---- epilogue: drain async, stage tile in smem, coalesced 128B stores
    CP_WAIT(0);
    __syncthreads();
    __nv_bfloat16* sOh = (__nv_bfloat16*)dynsmem;        // [128][66]
    __nv_bfloat16* sOl = sOh + 128 * STG_LDS;

    const int g = lane >> 2, t = lane & 3;
    #pragma unroll
    for (int i = 0; i < 4; i++) {
        const int r0 = wm * 64 + i * 16 + g;
        const int r1 = r0 + 8;
        const int m0 = by * 128 + r0;
        const int m1 = by * 128 + r1;
        float s0 = 0.f, s1 = 0.f;
        float inv0 = 0.f, inv1 = 0.f;
        if (MODE == 2) { inv0 = aux[auxbase + r0]; inv1 = aux[auxbase + r1]; }

        #pragma unroll
        for (int j = 0; j < NJ; j++) {
            float c0 = acc[i][j][0], c1 = acc[i][j][1];
            float c2 = acc[i][j][2], c3 = acc[i][j][3];
            float v0, v1, v2, v3;
            if (MODE == 1) {
                v0 = __expf(fmaf(c0, K_SCALE, -EXP_OFF));
                v1 = __expf(fmaf(c1, K_SCALE, -EXP_OFF));
                v2 = __expf(fmaf(c2, K_SCALE, -EXP_OFF));
                v3 = __expf(fmaf(c3, K_SCALE, -EXP_OFF));
                s0 += v0 + v1; s1 += v2 + v3;
            } else {
                v0 = c0 * inv0; v1 = c1 * inv0;
                v2 = c2 * inv1; v3 = c3 * inv1;
            }
            const int nloc = wn * 16 + j * 8 + 2 * t;
            *(uint32_t*)(sOh + r0 * STG_LDS + nloc) = pack_hi(v0, v1);
            *(uint32_t*)(sOl + r0 * STG_LDS + nloc) = pack_lo(v0, v1);
            *(uint32_t*)(sOh + r1 * STG_LDS + nloc) = pack_hi(v2, v3);
            *(uint32_t*)(sOl + r1 * STG_LDS + nloc) = pack_lo(v2, v3);
        }
        if (MODE == 1) {
            s0 += __shfl_xor_sync(0xffffffffu, s0, 1);
            s0 += __shfl_xor_sync(0xffffffffu, s0, 2);
            s1 += __shfl_xor_sync(0xffffffffu, s1, 1);
            s1 += __shfl_xor_sync(0xffffffffu, s1, 2);
            if (t == 0) {
                fout[((long long)bz * SEQL + m0) * 64 + bx * 4 + wn] = s0;
                fout[((long long)bz * SEQL + m1) * 64 + bx * 4 + wn] = s1;
            }
        }
    }
    __syncthreads();

    // copy-out: warp per row (32 uint32 = 128B), fully coalesced
    #pragma unroll
    for (int k = 0; k < 16; k++) {
        const int idx  = tid + k * 256;
        const int row  = idx >> 5;
        const int word = idx & 31;
        const uint32_t wh = *(const uint32_t*)(sOh + row * STG_LDS + word * 2);
        const uint32_t wl = *(const uint32_t*)(sOl + row * STG_LDS + word * 2);
        long long go;
        if (MODE == 1)
            go = (((long long)bz * SEQL + by * 128 + row) * SEQL + bx * 64) + word * 2;
        else
            go = (((long long)bb * SEQL + by * 128 + row) * EMB + hh * HD) + word * 2;
        *(uint32_t*)(ohi + go) = wh;
        *(uint32_t*)(olo + go) = wl;
    }
}

// ---------------------------------------------------------------------------
// fp32 -> bf16 hi/lo split
// ---------------------------------------------------------------------------
__global__ void split_hilo(const float* __restrict__ src,
                           __nv_bfloat16* __restrict__ hi,
                           __nv_bfloat16* __restrict__ lo, int n) {
    int i = blockIdx.x * 256 + threadIdx.x;
    if (i < n) {
        float v = src[i];
        __nv_bfloat16 h = __float2bfloat16(v);
        hi[i] = h;
        lo[i] = __float2bfloat16(v - __bfloat162float(h));
    }
}

// 64 partials per row -> 1/sum, half-range with offset
__global__ void inv_rows(const float* __restrict__ psum, float* __restrict__ inv,
                         int r0, int cnt) {
    int r = r0 + blockIdx.x * 256 + threadIdx.x;
    if (r < r0 + cnt) {
        float s = 0.f;
        #pragma unroll
        for (int j = 0; j < 64; j++) s += psum[(long long)r * 64 + j];
        inv[r] = 1.0f / s;
    }
}

// ---------------------------------------------------------------------------
// Launch: splits -> fork(two batch-half pipelines m0->m1->inv->m2) -> join -> m3
// ---------------------------------------------------------------------------
extern "C" void kernel_launch(void* const* d_in, const int* in_sizes, int n_in,
                              void* d_out, int out_size) {
    (void)in_sizes; (void)n_in; (void)out_size;
    const float* x      = (const float*)d_in[0];
    const float* w_qkv  = (const float*)d_in[1];
    const float* w_proj = (const float*)d_in[2];
    const float* b_proj = (const float*)d_in[3];

    float* out  = (float*)d_out;
    float* attn = out + (long long)ROWS * EMB;

    __nv_bfloat16 *xh, *xl, *wqh, *wql, *wph, *wpl, *qh, *ql, *ph, *pl, *ohh, *ohl;
    float *psum, *inv;
    cudaGetSymbolAddress((void**)&xh,  g_x_hi);    cudaGetSymbolAddress((void**)&xl,  g_x_lo);
    cudaGetSymbolAddress((void**)&wqh, g_wqkv_hi); cudaGetSymbolAddress((void**)&wql, g_wqkv_lo);
    cudaGetSymbolAddress((void**)&wph, g_wp_hi);   cudaGetSymbolAddress((void**)&wpl, g_wp_lo);
    cudaGetSymbolAddress((void**)&qh,  g_qkv_hi);  cudaGetSymbolAddress((void**)&ql,  g_qkv_lo);
    cudaGetSymbolAddress((void**)&ph,  g_p_hi);    cudaGetSymbolAddress((void**)&pl,  g_p_lo);
    cudaGetSymbolAddress((void**)&ohh, g_oh_hi);   cudaGetSymbolAddress((void**)&ohl, g_oh_lo);
    cudaGetSymbolAddress((void**)&psum, g_psum);   cudaGetSymbolAddress((void**)&inv,  g_inv);

    constexpr int SMBIG = 3 * 61440;  // 184320
    constexpr int SM1   = 2 * 30720;  //  61440  (>= staging 33792)
    constexpr int SM2   = 3 * 29696;  //  89088  (>= staging 33792)

    static cudaStream_t sA = nullptr, sB = nullptr;
    static cudaEvent_t evFork = nullptr, evA = nullptr, evB = nullptr;
    static bool init_done = false;
    if (!init_done) {
        cudaFuncSetAttribute(gemm_big<0>, cudaFuncAttributeMaxDynamicSharedMemorySize, SMBIG);
        cudaFuncSetAttribute(gemm_big<3>, cudaFuncAttributeMaxDynamicSharedMemorySize, SMBIG);
        cudaFuncSetAttribute(mma_gemm<1>, cudaFuncAttributeMaxDynamicSharedMemorySize, SM1);
        cudaFuncSetAttribute(mma_gemm<2>, cudaFuncAttributeMaxDynamicSharedMemorySize, SM2);
        cudaStreamCreateWithFlags(&sA, cudaStreamNonBlocking);
        cudaStreamCreateWithFlags(&sB, cudaStreamNonBlocking);
        cudaEventCreateWithFlags(&evFork, cudaEventDisableTiming);
        cudaEventCreateWithFlags(&evA, cudaEventDisableTiming);
        cudaEventCreateWithFlags(&evB, cudaEventDisableTiming);
        init_done = true;
    }

    // 0) hi/lo splits on the main stream
    split_hilo<<<(ROWS*EMB + 255)/256, 256>>>(x, xh, xl, ROWS*EMB);
    split_hilo<<<(QKVC*EMB + 255)/256, 256>>>(w_qkv, wqh, wql, QKVC*EMB);
    split_hilo<<<(EMB*EMB + 255)/256, 256>>>(w_proj, wph, wpl, EMB*EMB);

    // fork
    cudaEventRecord(evFork, 0);
    cudaStreamWaitEvent(sA, evFork, 0);
    cudaStreamWaitEvent(sB, evFork, 0);

    // --- half pipeline A: batches 0-3 (rows 0..4095, z 0..47) ---
    gemm_big<0><<<dim3(QKVC/128, 16), 256, SMBIG, sA>>>(
        xh, xl, wqh, wql, nullptr, qh, ql, nullptr, 0);
    mma_gemm<1><<<dim3(16, 8, 48), 256, SM1, sA>>>(
        qh, ql, qh, ql, psum, ph, pl, nullptr, 0);
    inv_rows<<<(AROWS/2 + 255)/256, 256, 0, sA>>>(psum, inv, 0, AROWS/2);
    mma_gemm<2><<<dim3(1, 8, 48), 256, SM2, sA>>>(
        ph, pl, qh, ql, attn, ohh, ohl, inv, 0);
    cudaEventRecord(evA, sA);

    // --- half pipeline B: batches 4-7 (rows 4096..8191, z 48..95) ---
    gemm_big<0><<<dim3(QKVC/128, 16), 256, SMBIG, sB>>>(
        xh, xl, wqh, wql, nullptr, qh, ql, nullptr, 16);
    mma_gemm<1><<<dim3(16, 8, 48), 256, SM1, sB>>>(
        qh, ql, qh, ql, psum, ph, pl, nullptr, 48);
    inv_rows<<<(AROWS/2 + 255)/256, 256, 0, sB>>>(psum, inv, AROWS/2, AROWS/2);
    mma_gemm<2><<<dim3(1, 8, 48), 256, SM2, sB>>>(
        ph, pl, qh, ql, attn, ohh, ohl, inv, 48);
    cudaEventRecord(evB, sB);

    // join
    cudaStreamWaitEvent(0, evA, 0);
    cudaStreamWaitEvent(0, evB, 0);

    // 5) Output projection + bias -> fp32 out (needs all heads)
    gemm_big<3><<<dim3(EMB/128, ROWS/256), 256, SMBIG>>>(
        ohh, ohl, wph, wpl, out, nullptr, nullptr, b_proj, 0);
}

// round 14
// speedup vs baseline: 1.0767x; 1.0609x over previous
#include <cuda_runtime.h>
#include <cuda_bf16.h>
#include <cstdint>

// ---------------------------------------------------------------------------
// Problem constants
// ---------------------------------------------------------------------------
#define BATCHN  8
#define SEQL    1024
#define EMB     768
#define NH      12
#define HD      64
#define ROWS    (BATCHN*SEQL)        // 8192
#define QKVC    (3*EMB)              // 2304
#define ZTOT    (BATCHN*NH)          // 96
#define AROWS   (ZTOT*SEQL)          // 98304
#define K_SCALE 0.125f
#define EXP_OFF 20.0f

// ---------------------------------------------------------------------------
// Device scratch (static globals; allocation-free)
// ---------------------------------------------------------------------------
__device__ __align__(16) __nv_bfloat16 g_x_hi  [ROWS*EMB];
__device__ __align__(16) __nv_bfloat16 g_x_lo  [ROWS*EMB];
__device__ __align__(16) __nv_bfloat16 g_wqkv_hi[QKVC*EMB];
__device__ __align__(16) __nv_bfloat16 g_wqkv_lo[QKVC*EMB];
__device__ __align__(16) __nv_bfloat16 g_wp_hi [EMB*EMB];
__device__ __align__(16) __nv_bfloat16 g_wp_lo [EMB*EMB];
__device__ __align__(16) __nv_bfloat16 g_qkv_hi[(size_t)ROWS*QKVC];
__device__ __align__(16) __nv_bfloat16 g_qkv_lo[(size_t)ROWS*QKVC];
__device__ __align__(16) __nv_bfloat16 g_p_hi  [(size_t)ZTOT*SEQL*SEQL];
__device__ __align__(16) __nv_bfloat16 g_p_lo  [(size_t)ZTOT*SEQL*SEQL];
__device__ __align__(16) __nv_bfloat16 g_oh_hi [ROWS*EMB];
__device__ __align__(16) __nv_bfloat16 g_oh_lo [ROWS*EMB];
__device__ float g_psum[(size_t)AROWS*64];
__device__ float g_inv [AROWS];

// ---------------------------------------------------------------------------
// PTX helpers (all sm_80-era: safe on plain compute_103)
// ---------------------------------------------------------------------------
__device__ __forceinline__ uint32_t smem_u32(const void* p) {
    uint32_t a;
    asm("{ .reg .u64 t; cvta.to.shared.u64 t, %1; cvt.u32.u64 %0, t; }"
        : "=r"(a) : "l"(p));
    return a;
}
__device__ __forceinline__ void cp16(uint32_t dst, const void* src) {
    asm volatile("cp.async.cg.shared.global [%0], [%1], 16;"
                 :: "r"(dst), "l"(src));
}
#define CP_COMMIT() asm volatile("cp.async.commit_group;" ::: "memory")
#define CP_WAIT(n)  asm volatile("cp.async.wait_group %0;" :: "n"(n) : "memory")

__device__ __forceinline__ void ldsm_x4(uint32_t* r, uint32_t addr) {
    asm volatile("ldmatrix.sync.aligned.m8n8.x4.shared.b16 {%0,%1,%2,%3}, [%4];"
        : "=r"(r[0]), "=r"(r[1]), "=r"(r[2]), "=r"(r[3]) : "r"(addr));
}
__device__ __forceinline__ void ldsm_x2(uint32_t* r, uint32_t addr) {
    asm volatile("ldmatrix.sync.aligned.m8n8.x2.shared.b16 {%0,%1}, [%2];"
        : "=r"(r[0]), "=r"(r[1]) : "r"(addr));
}
__device__ __forceinline__ void ldsm_x2t(uint32_t* r, uint32_t addr) {
    asm volatile("ldmatrix.sync.aligned.m8n8.x2.trans.shared.b16 {%0,%1}, [%2];"
        : "=r"(r[0]), "=r"(r[1]) : "r"(addr));
}
__device__ __forceinline__ void mma_bf16(float* c, const uint32_t* a, const uint32_t* b) {
    asm volatile("mma.sync.aligned.m16n8k16.row.col.f32.bf16.bf16.f32 "
        "{%0,%1,%2,%3}, {%4,%5,%6,%7}, {%8,%9}, {%0,%1,%2,%3};"
        : "+f"(c[0]), "+f"(c[1]), "+f"(c[2]), "+f"(c[3])
        : "r"(a[0]), "r"(a[1]), "r"(a[2]), "r"(a[3]), "r"(b[0]), "r"(b[1]));
}

__device__ __forceinline__ uint32_t pack_hi(float a, float b) {
    return ((uint32_t)__bfloat16_as_ushort(__float2bfloat16(b)) << 16) |
            (uint32_t)__bfloat16_as_ushort(__float2bfloat16(a));
}
__device__ __forceinline__ uint32_t pack_lo(float a, float b) {
    __nv_bfloat16 ha = __float2bfloat16(a), hb = __float2bfloat16(b);
    float la = a - __bfloat162float(ha), lb = b - __bfloat162float(hb);
    return ((uint32_t)__bfloat16_as_ushort(__float2bfloat16(lb)) << 16) |
            (uint32_t)__bfloat16_as_ushort(__float2bfloat16(la));
}

// ---------------------------------------------------------------------------
// BIG-TILE projection GEMM (modes 0 and 3). 256x128 tile, 8 warps,
// 3-stage cp.async ring, unconditional commit. by0 = row-block offset.
// ---------------------------------------------------------------------------
template<int MODE>
__global__ __launch_bounds__(256)
void gemm_big(const __nv_bfloat16* __restrict__ Ahi_base,
              const __nv_bfloat16* __restrict__ Alo_base,
              const __nv_bfloat16* __restrict__ Bhi_base,
              const __nv_bfloat16* __restrict__ Blo_base,
              float* __restrict__ fout,
              __nv_bfloat16* __restrict__ ohi,
              __nv_bfloat16* __restrict__ olo,
              const float* __restrict__ bias,
              int by0) {
    constexpr int NSTAGE  = EMB / 32;           // 24
    constexpr int STAGES  = 3;
    constexpr int LDS     = 40;
    constexpr int A_BYTES = 256 * LDS * 2;      // 20480
    constexpr int B_BYTES = 128 * LDS * 2;      // 10240
    constexpr int STAGE_B = 2 * A_BYTES + 2 * B_BYTES;   // 61440

    extern __shared__ __align__(16) char dynsmem[];

    const int tid  = threadIdx.x;
    const int lane = tid & 31;
    const int wid  = tid >> 5;
    const int wm   = wid & 3;
    const int wn   = wid >> 2;
    const int l15  = lane & 15;
    const int bx = blockIdx.x, by = blockIdx.y + by0;

    const __nv_bfloat16* Ah = Ahi_base + (long long)by * 256 * EMB;
    const __nv_bfloat16* Al = Alo_base + (long long)by * 256 * EMB;
    const __nv_bfloat16* Bh = Bhi_base + (long long)bx * 128 * EMB;
    const __nv_bfloat16* Bl = Blo_base + (long long)bx * 128 * EMB;

    const int arow = tid >> 2;
    const int acol = (tid & 3) * 8;

    const uint32_t sb = smem_u32(dynsmem);

    auto issue = [&](int s) {
        const uint32_t base = sb + (uint32_t)(s % STAGES) * STAGE_B;
        const long long k0 = (long long)s * 32;
        #pragma unroll
        for (int it = 0; it < 4; it++) {
            const int r = arow + it * 64;
            const uint32_t d = base + (uint32_t)(r * LDS + acol) * 2;
            cp16(d,           Ah + (long long)r * EMB + k0 + acol);
            cp16(d + A_BYTES, Al + (long long)r * EMB + k0 + acol);
        }
        #pragma unroll
        for (int it = 0; it < 2; it++) {
            const int r = arow + it * 64;
            const uint32_t d = base + 2 * A_BYTES + (uint32_t)(r * LDS + acol) * 2;
            cp16(d,           Bh + (long long)r * EMB + k0 + acol);
            cp16(d + B_BYTES, Bl + (long long)r * EMB + k0 + acol);
        }
    };

    float acc[4][8][4];
    #pragma unroll
    for (int i = 0; i < 4; i++)
        #pragma unroll
        for (int j = 0; j < 8; j++)
            #pragma unroll
            for (int e = 0; e < 4; e++) acc[i][j][e] = 0.f;

    issue(0); CP_COMMIT();
    issue(1); CP_COMMIT();

    for (int s = 0; s < NSTAGE; s++) {
        CP_WAIT(1);
        __syncthreads();
        if (s + 2 < NSTAGE) issue(s + 2);
        CP_COMMIT();

        const uint32_t base = sb + (uint32_t)(s % STAGES) * STAGE_B;
        const uint32_t uAh = base;
        const uint32_t uAl = base + A_BYTES;
        const uint32_t uBh = base + 2 * A_BYTES;
        const uint32_t uBl = base + 2 * A_BYTES + B_BYTES;

        #pragma unroll
        for (int ks = 0; ks < 2; ks++) {
            uint32_t bh[8][2], bl[8][2];
            #pragma unroll
            for (int j = 0; j < 8; j++) {
                const int nr = wn * 64 + j * 8 + (l15 & 7);
                const int kc = ks * 16 + (l15 >> 3) * 8;
                const uint32_t off = (uint32_t)(nr * LDS + kc) * 2;
                ldsm_x2(bh[j], uBh + off);
                ldsm_x2(bl[j], uBl + off);
            }
            #pragma unroll
            for (int i = 0; i < 4; i++) {
                const int ar = wm * 64 + i * 16 + l15;
                const int ac = ks * 16 + (lane >> 4) * 8;
                const uint32_t aoff = (uint32_t)(ar * LDS + ac) * 2;
                uint32_t ah[4], al[4];
                ldsm_x4(ah, uAh + aoff);
                #pragma unroll
                for (int j = 0; j < 8; j++) mma_bf16(acc[i][j], ah, bh[j]);
                ldsm_x4(al, uAl + aoff);
                #pragma unroll
                for (int j = 0; j < 8; j++) mma_bf16(acc[i][j], ah, bl[j]);
                #pragma unroll
                for (int j = 0; j < 8; j++) mma_bf16(acc[i][j], al, bh[j]);
            }
        }
    }

    // ---- epilogue ----
    const int g = lane >> 2, t = lane & 3;
    #pragma unroll
    for (int i = 0; i < 4; i++) {
        const int m0 = by * 256 + wm * 64 + i * 16 + g;
        const int m1 = m0 + 8;
        #pragma unroll
        for (int j = 0; j < 8; j++) {
            const int n = bx * 128 + wn * 64 + j * 8 + 2 * t;
            const float c0 = acc[i][j][0], c1 = acc[i][j][1];
            const float c2 = acc[i][j][2], c3 = acc[i][j][3];
            if (MODE == 0) {
                long long o0 = (long long)m0 * QKVC + n;
                long long o1 = (long long)m1 * QKVC + n;
                *(uint32_t*)(ohi + o0) = pack_hi(c0, c1);
                *(uint32_t*)(olo + o0) = pack_lo(c0, c1);
                *(uint32_t*)(ohi + o1) = pack_hi(c2, c3);
                *(uint32_t*)(olo + o1) = pack_lo(c2, c3);
            } else {
                float2 w0 = { c0 + bias[n], c1 + bias[n + 1] };
                float2 w1 = { c2 + bias[n], c3 + bias[n + 1] };
                *(float2*)(fout + (long long)m0 * EMB + n) = w0;
                *(float2*)(fout + (long long)m1 * EMB + n) = w1;
            }
        }
    }
}

// ---------------------------------------------------------------------------
// Attention kernels (modes 1 and 2), 128x64 tile, 2 CTAs/SM, staged
// coalesced epilogues. z0 = head-batch offset.
// ---------------------------------------------------------------------------
#define STG_LDS 66

template<int MODE>
__global__ __launch_bounds__(256, 2)
void mma_gemm(const __nv_bfloat16* __restrict__ Ahi_base,
              const __nv_bfloat16* __restrict__ Alo_base,
              const __nv_bfloat16* __restrict__ Bhi_base,
              const __nv_bfloat16* __restrict__ Blo_base,
              float* __restrict__ fout,
              __nv_bfloat16* __restrict__ ohi,
              __nv_bfloat16* __restrict__ olo,
              const float* __restrict__ aux,
              int z0) {
    constexpr int NJ      = 2;
    constexpr int KTOT    = (MODE == 1) ? 64 : 1024;
    constexpr int NSTAGE  = KTOT / 32;
    constexpr int STAGES  = (MODE == 1) ? 2 : 3;
    constexpr int LDS_A   = 40;
    constexpr int LDS_B   = (MODE == 2) ? 72 : 40;
    constexpr int A_BYTES = 128 * LDS_A * 2;
    constexpr int B_BYTES = (MODE == 2) ? 32 * LDS_B * 2 : 64 * LDS_B * 2;
    constexpr int STAGE_B = 2 * A_BYTES + 2 * B_BYTES;

    extern __shared__ __align__(16) char dynsmem[];

    const int tid  = threadIdx.x;
    const int lane = tid & 31;
    const int wid  = tid >> 5;
    const int wm   = wid >> 2;
    const int wn   = wid & 3;
    const int l15  = lane & 15;
    const int bx = blockIdx.x, by = blockIdx.y, bz = blockIdx.z + z0;
    const int bb = bz / NH, hh = bz % NH;

    const __nv_bfloat16 *Ah, *Al, *Bh, *Bl;
    long long LDA = 0, LDB = 0;
    if (MODE == 1) {
        LDA = QKVC; LDB = QKVC;
        long long ao = ((long long)bb * SEQL + by * 128) * QKVC + hh * HD;
        long long bo = ((long long)bb * SEQL + bx * 64) * QKVC + EMB + hh * HD;
        Ah = Ahi_base + ao; Al = Alo_base + ao;
        Bh = Bhi_base + bo; Bl = Blo_base + bo;
    } else {
        LDA = SEQL; LDB = QKVC;
        long long ao = (long long)bz * SEQL * SEQL + (long long)by * 128 * SEQL;
        Ah = Ahi_base + ao; Al = Alo_base + ao;
        Bh = Bhi_base;      Bl = Blo_base;
    }
    float* attn_tile = nullptr;
    if (MODE == 2)
        attn_tile = fout + (long long)bz * SEQL * SEQL + (long long)by * 128 * SEQL;
    const long long auxbase = (MODE == 2) ? ((long long)bz * SEQL + by * 128) : 0;

    const int arow0 = tid >> 2;
    const int acol  = (tid & 3) * 8;
    const int arow1 = arow0 + 64;
    const int brow2 = tid >> 3;
    const int bcol2 = (tid & 7) * 8;

    const uint32_t sb = smem_u32(dynsmem);

    auto issue = [&](int s) {
        const uint32_t base = sb + (uint32_t)(s % STAGES) * STAGE_B;
        const long long k0 = (long long)s * 32;
        const uint32_t dA0 = base + (uint32_t)(arow0 * LDS_A + acol) * 2;
        const uint32_t dA1 = base + (uint32_t)(arow1 * LDS_A + acol) * 2;
        cp16(dA0,           Ah + (long long)arow0 * LDA + k0 + acol);
        cp16(dA1,           Ah + (long long)arow1 * LDA + k0 + acol);
        cp16(dA0 + A_BYTES, Al + (long long)arow0 * LDA + k0 + acol);
        cp16(dA1 + A_BYTES, Al + (long long)arow1 * LDA + k0 + acol);
        if (MODE != 2) {
            const uint32_t dB = base + 2 * A_BYTES + (uint32_t)(arow0 * LDS_B + acol) * 2;
            cp16(dB,           Bh + (long long)arow0 * LDB + k0 + acol);
            cp16(dB + B_BYTES, Bl + (long long)arow0 * LDB + k0 + acol);
        } else {
            long long vo = ((long long)bb * SEQL + s * 32 + brow2) * QKVC
                         + 2 * EMB + hh * HD + bcol2;
            const uint32_t dB = base + 2 * A_BYTES + (uint32_t)(brow2 * LDS_B + bcol2) * 2;
            cp16(dB,           Bh + vo);
            cp16(dB + B_BYTES, Bl + vo);
        }
    };

    float acc[4][NJ][4];
    #pragma unroll
    for (int i = 0; i < 4; i++)
        #pragma unroll
        for (int j = 0; j < NJ; j++)
            #pragma unroll
            for (int e = 0; e < 4; e++) acc[i][j][e] = 0.f;

    #pragma unroll
    for (int p = 0; p < STAGES - 1 && p < NSTAGE; p++) { issue(p); CP_COMMIT(); }

    for (int s = 0; s < NSTAGE; s++) {
        CP_WAIT(STAGES - 2);
        __syncthreads();
        if (s + STAGES - 1 < NSTAGE) issue(s + STAGES - 1);
        CP_COMMIT();

        const int slot = s % STAGES;
        const uint32_t base = sb + (uint32_t)slot * STAGE_B;

        if (MODE == 2) {
            #pragma unroll
            for (int cch = 0; cch < 2; cch++) {
                const int r = (cch == 0) ? arow0 : arow1;
                const char* sp = dynsmem + slot * STAGE_B + (r * LDS_A + acol) * 2;
                uint4 vh = *(const uint4*)sp;
                uint4 vl = *(const uint4*)(sp + A_BYTES);
                const __nv_bfloat16* eh = (const __nv_bfloat16*)&vh;
                const __nv_bfloat16* el = (const __nv_bfloat16*)&vl;
                const float iv = aux[auxbase + r];
                long long ab = (long long)r * SEQL + s * 32 + acol;
                float4 o0, o1;
                o0.x = (__bfloat162float(eh[0]) + __bfloat162float(el[0])) * iv;
                o0.y = (__bfloat162float(eh[1]) + __bfloat162float(el[1])) * iv;
                o0.z = (__bfloat162float(eh[2]) + __bfloat162float(el[2])) * iv;
                o0.w = (__bfloat162float(eh[3]) + __bfloat162float(el[3])) * iv;
                o1.x = (__bfloat162float(eh[4]) + __bfloat162float(el[4])) * iv;
                o1.y = (__bfloat162float(eh[5]) + __bfloat162float(el[5])) * iv;
                o1.z = (__bfloat162float(eh[6]) + __bfloat162float(el[6])) * iv;
                o1.w = (__bfloat162float(eh[7]) + __bfloat162float(el[7])) * iv;
                *(float4*)(attn_tile + ab)     = o0;
                *(float4*)(attn_tile + ab + 4) = o1;
            }
        }

        const uint32_t uAh = base;
        const uint32_t uAl = base + A_BYTES;
        const uint32_t uBh = base + 2 * A_BYTES;
        const uint32_t uBl = base + 2 * A_BYTES + B_BYTES;

        #pragma unroll
        for (int ks = 0; ks < 2; ks++) {
            uint32_t bh[NJ][2], bl[NJ][2];
            #pragma unroll
            for (int j = 0; j < NJ; j++) {
                if (MODE == 2) {
                    const int kr = ks * 16 + l15;
                    const int nc = wn * 16 + j * 8;
                    const uint32_t off = (uint32_t)(kr * LDS_B + nc) * 2;
                    ldsm_x2t(bh[j], uBh + off);
                    ldsm_x2t(bl[j], uBl + off);
                } else {
                    const int nr = wn * 16 + j * 8 + (l15 & 7);
                    const int kc = ks * 16 + (l15 >> 3) * 8;
                    const uint32_t off = (uint32_t)(nr * LDS_B + kc) * 2;
                    ldsm_x2(bh[j], uBh + off);
                    ldsm_x2(bl[j], uBl + off);
                }
            }
            #pragma unroll
            for (int i = 0; i < 4; i++) {
                const int ar = wm * 64 + i * 16 + l15;
                const int ac = ks * 16 + (lane >> 4) * 8;
                const uint32_t aoff = (uint32_t)(ar * LDS_A + ac) * 2;
                uint32_t ah[4], al[4];
                ldsm_x4(ah, uAh + aoff);
                #pragma unroll
                for (int j = 0; j < NJ; j++) mma_bf16(acc[i][j], ah, bh[j]);
                ldsm_x4(al, uAl + aoff);
                #pragma unroll
                for (int j = 0; j < NJ; j++) mma_bf16(acc[i][j], ah, bl[j]);
                #pragma unroll
                for (int j = 0; j < NJ; j++) mma_bf16(acc[i][j], al, bh[j]);
            }
        }
        __syncthreads();
    }

    // ---- epilogue: drain async, stage tile in smem, coalesced 128B stores
    CP_WAIT(0);
    __syncthreads();
    __nv_bfloat16* sOh = (__nv_bfloat16*)dynsmem;        // [128][66]
    __nv_bfloat16* sOl = sOh + 128 * STG_LDS;

    const int g = lane >> 2, t = lane & 3;
    #pragma unroll
    for (int i = 0; i < 4; i++) {
        const int r0 = wm * 64 + i * 16 + g;
        const int r1 = r0 + 8;
        const int m0 = by * 128 + r0;
        const int m1 = by * 128 + r1;
        float s0 = 0.f, s1 = 0.f;
        float inv0 = 0.f, inv1 = 0.f;
        if (MODE == 2) { inv0 = aux[auxbase + r0]; inv1 = aux[auxbase + r1]; }

        #pragma unroll
        for (int j = 0; j < NJ; j++) {
            float c0 = acc[i][j][0], c1 = acc[i][j][1];
            float c2 = acc[i][j][2], c3 = acc[i][j][3];
            float v0, v1, v2, v3;
            if (MODE == 1) {
                v0 = __expf(fmaf(c0, K_SCALE, -EXP_OFF));
                v1 = __expf(fmaf(c1, K_SCALE, -EXP_OFF));
                v2 = __expf(fmaf(c2, K_SCALE, -EXP_OFF));
                v3 = __expf(fmaf(c3, K_SCALE, -EXP_OFF));
                s0 += v0 + v1; s1 += v2 + v3;
            } else {
                v0 = c0 * inv0; v1 = c1 * inv0;
                v2 = c2 * inv1; v3 = c3 * inv1;
            }
            const int nloc = wn * 16 + j * 8 + 2 * t;
            *(uint32_t*)(sOh + r0 * STG_LDS + nloc) = pack_hi(v0, v1);
            *(uint32_t*)(sOl + r0 * STG_LDS + nloc) = pack_lo(v0, v1);
            *(uint32_t*)(sOh + r1 * STG_LDS + nloc) = pack_hi(v2, v3);
            *(uint32_t*)(sOl + r1 * STG_LDS + nloc) = pack_lo(v2, v3);
        }
        if (MODE == 1) {
            s0 += __shfl_xor_sync(0xffffffffu, s0, 1);
            s0 += __shfl_xor_sync(0xffffffffu, s0, 2);
            s1 += __shfl_xor_sync(0xffffffffu, s1, 1);
            s1 += __shfl_xor_sync(0xffffffffu, s1, 2);
            if (t == 0) {
                fout[((long long)bz * SEQL + m0) * 64 + bx * 4 + wn] = s0;
                fout[((long long)bz * SEQL + m1) * 64 + bx * 4 + wn] = s1;
            }
        }
    }
    __syncthreads();

    #pragma unroll
    for (int k = 0; k < 16; k++) {
        const int idx  = tid + k * 256;
        const int row  = idx >> 5;
        const int word = idx & 31;
        const uint32_t wh = *(const uint32_t*)(sOh + row * STG_LDS + word * 2);
        const uint32_t wl = *(const uint32_t*)(sOl + row * STG_LDS + word * 2);
        long long go;
        if (MODE == 1)
            go = (((long long)bz * SEQL + by * 128 + row) * SEQL + bx * 64) + word * 2;
        else
            go = (((long long)bb * SEQL + by * 128 + row) * EMB + hh * HD) + word * 2;
        *(uint32_t*)(ohi + go) = wh;
        *(uint32_t*)(olo + go) = wl;
    }
}

// ---------------------------------------------------------------------------
// fp32 -> bf16 hi/lo split
// ---------------------------------------------------------------------------
__global__ void split_hilo(const float* __restrict__ src,
                           __nv_bfloat16* __restrict__ hi,
                           __nv_bfloat16* __restrict__ lo, int n) {
    int i = blockIdx.x * 256 + threadIdx.x;
    if (i < n) {
        float v = src[i];
        __nv_bfloat16 h = __float2bfloat16(v);
        hi[i] = h;
        lo[i] = __float2bfloat16(v - __bfloat162float(h));
    }
}

// 64 partials per row -> 1/sum, half-range with offset
__global__ void inv_rows(const float* __restrict__ psum, float* __restrict__ inv,
                         int r0, int cnt) {
    int r = r0 + blockIdx.x * 256 + threadIdx.x;
    if (r < r0 + cnt) {
        float s = 0.f;
        #pragma unroll
        for (int j = 0; j < 64; j++) s += psum[(long long)r * 64 + j];
        inv[r] = 1.0f / s;
    }
}

// ---------------------------------------------------------------------------
// Launch: two fully independent batch-half pipelines incl. m3 halves.
// s0: w_qkv split (gates m0) then w_proj split (gates only m3 halves).
// sA/sB: x-half split -> m0 -> m1 -> inv -> m2 -> m3(half).
// ---------------------------------------------------------------------------
extern "C" void kernel_launch(void* const* d_in, const int* in_sizes, int n_in,
                              void* d_out, int out_size) {
    (void)in_sizes; (void)n_in; (void)out_size;
    const float* x      = (const float*)d_in[0];
    const float* w_qkv  = (const float*)d_in[1];
    const float* w_proj = (const float*)d_in[2];
    const float* b_proj = (const float*)d_in[3];

    float* out  = (float*)d_out;
    float* attn = out + (long long)ROWS * EMB;

    __nv_bfloat16 *xh, *xl, *wqh, *wql, *wph, *wpl, *qh, *ql, *ph, *pl, *ohh, *ohl;
    float *psum, *inv;
    cudaGetSymbolAddress((void**)&xh,  g_x_hi);    cudaGetSymbolAddress((void**)&xl,  g_x_lo);
    cudaGetSymbolAddress((void**)&wqh, g_wqkv_hi); cudaGetSymbolAddress((void**)&wql, g_wqkv_lo);
    cudaGetSymbolAddress((void**)&wph, g_wp_hi);   cudaGetSymbolAddress((void**)&wpl, g_wp_lo);
    cudaGetSymbolAddress((void**)&qh,  g_qkv_hi);  cudaGetSymbolAddress((void**)&ql,  g_qkv_lo);
    cudaGetSymbolAddress((void**)&ph,  g_p_hi);    cudaGetSymbolAddress((void**)&pl,  g_p_lo);
    cudaGetSymbolAddress((void**)&ohh, g_oh_hi);   cudaGetSymbolAddress((void**)&ohl, g_oh_lo);
    cudaGetSymbolAddress((void**)&psum, g_psum);   cudaGetSymbolAddress((void**)&inv,  g_inv);

    constexpr int SMBIG = 3 * 61440;  // 184320
    constexpr int SM1   = 2 * 30720;  //  61440
    constexpr int SM2   = 3 * 29696;  //  89088
    constexpr int HALF_X = ROWS * EMB / 2;

    static cudaStream_t sA = nullptr, sB = nullptr;
    static cudaEvent_t evWq = nullptr, evWp = nullptr, evA = nullptr, evB = nullptr;
    static bool init_done = false;
    if (!init_done) {
        cudaFuncSetAttribute(gemm_big<0>, cudaFuncAttributeMaxDynamicSharedMemorySize, SMBIG);
        cudaFuncSetAttribute(gemm_big<3>, cudaFuncAttributeMaxDynamicSharedMemorySize, SMBIG);
        cudaFuncSetAttribute(mma_gemm<1>, cudaFuncAttributeMaxDynamicSharedMemorySize, SM1);
        cudaFuncSetAttribute(mma_gemm<2>, cudaFuncAttributeMaxDynamicSharedMemorySize, SM2);
        cudaStreamCreateWithFlags(&sA, cudaStreamNonBlocking);
        cudaStreamCreateWithFlags(&sB, cudaStreamNonBlocking);
        cudaEventCreateWithFlags(&evWq, cudaEventDisableTiming);
        cudaEventCreateWithFlags(&evWp, cudaEventDisableTiming);
        cudaEventCreateWithFlags(&evA, cudaEventDisableTiming);
        cudaEventCreateWithFlags(&evB, cudaEventDisableTiming);
        init_done = true;
    }

    // s0: weight splits. w_qkv gates m0; w_proj gates only m3 halves.
    split_hilo<<<(QKVC*EMB + 255)/256, 256>>>(w_qkv, wqh, wql, QKVC*EMB);
    cudaEventRecord(evWq, 0);
    split_hilo<<<(EMB*EMB + 255)/256, 256>>>(w_proj, wph, wpl, EMB*EMB);
    cudaEventRecord(evWp, 0);

    // --- pipeline A: batches 0-3 (rows 0..4095, z 0..47, m3 by 0..15) ---
    split_hilo<<<(HALF_X + 255)/256, 256, 0, sA>>>(x, xh, xl, HALF_X);
    cudaStreamWaitEvent(sA, evWq, 0);
    gemm_big<0><<<dim3(QKVC/128, 16), 256, SMBIG, sA>>>(
        xh, xl, wqh, wql, nullptr, qh, ql, nullptr, 0);
    mma_gemm<1><<<dim3(16, 8, 48), 256, SM1, sA>>>(
        qh, ql, qh, ql, psum, ph, pl, nullptr, 0);
    inv_rows<<<(AROWS/2 + 255)/256, 256, 0, sA>>>(psum, inv, 0, AROWS/2);
    mma_gemm<2><<<dim3(1, 8, 48), 256, SM2, sA>>>(
        ph, pl, qh, ql, attn, ohh, ohl, inv, 0);
    cudaStreamWaitEvent(sA, evWp, 0);
    gemm_big<3><<<dim3(EMB/128, 16), 256, SMBIG, sA>>>(
        ohh, ohl, wph, wpl, out, nullptr, nullptr, b_proj, 0);
    cudaEventRecord(evA, sA);

    // --- pipeline B: batches 4-7 (rows 4096..8191, z 48..95, m3 by 16..31) ---
    split_hilo<<<(HALF_X + 255)/256, 256, 0, sB>>>(x + HALF_X, xh + HALF_X, xl + HALF_X, HALF_X);
    cudaStreamWaitEvent(sB, evWq, 0);
    gemm_big<0><<<dim3(QKVC/128, 16), 256, SMBIG, sB>>>(
        xh, xl, wqh, wql, nullptr, qh, ql, nullptr, 16);
    mma_gemm<1><<<dim3(16, 8, 48), 256, SM1, sB>>>(
        qh, ql, qh, ql, psum, ph, pl, nullptr, 48);
    inv_rows<<<(AROWS/2 + 255)/256, 256, 0, sB>>>(psum, inv, AROWS/2, AROWS/2);
    mma_gemm<2><<<dim3(1, 8, 48), 256, SM2, sB>>>(
        ph, pl, qh, ql, attn, ohh, ohl, inv, 48);
    cudaStreamWaitEvent(sB, evWp, 0);
    gemm_big<3><<<dim3(EMB/128, 16), 256, SMBIG, sB>>>(
        ohh, ohl, wph, wpl, out, nullptr, nullptr, b_proj, 16);
    cudaEventRecord(evB, sB);

    // join into the caller's stream
    cudaStreamWaitEvent(0, evA, 0);
    cudaStreamWaitEvent(0, evB, 0);
}

// round 15
// speedup vs baseline: 1.3108x; 1.2175x over previous
#include <cuda_runtime.h>
#include <cuda_bf16.h>
#include <cstdint>

// ---------------------------------------------------------------------------
// Problem constants
// ---------------------------------------------------------------------------
#define BATCHN  8
#define SEQL    1024
#define EMB     768
#define NH      12
#define HD      64
#define ROWS    (BATCHN*SEQL)        // 8192
#define QKVC    (3*EMB)              // 2304
#define ZTOT    (BATCHN*NH)          // 96
#define K_SCALE 0.125f
#define EXP_OFF 20.0f

// ---------------------------------------------------------------------------
// Device scratch (static globals; allocation-free)
// ---------------------------------------------------------------------------
__device__ __align__(16) __nv_bfloat16 g_x_hi  [ROWS*EMB];
__device__ __align__(16) __nv_bfloat16 g_x_lo  [ROWS*EMB];
__device__ __align__(16) __nv_bfloat16 g_wqkv_hi[QKVC*EMB];
__device__ __align__(16) __nv_bfloat16 g_wqkv_lo[QKVC*EMB];
__device__ __align__(16) __nv_bfloat16 g_wp_hi [EMB*EMB];
__device__ __align__(16) __nv_bfloat16 g_wp_lo [EMB*EMB];
__device__ __align__(16) __nv_bfloat16 g_qkv_hi[(size_t)ROWS*QKVC];
__device__ __align__(16) __nv_bfloat16 g_qkv_lo[(size_t)ROWS*QKVC];
__device__ __align__(16) __nv_bfloat16 g_oh_hi [ROWS*EMB];
__device__ __align__(16) __nv_bfloat16 g_oh_lo [ROWS*EMB];

// ---------------------------------------------------------------------------
// PTX helpers (all sm_80-era: safe on plain compute_103)
// ---------------------------------------------------------------------------
__device__ __forceinline__ uint32_t smem_u32(const void* p) {
    uint32_t a;
    asm("{ .reg .u64 t; cvta.to.shared.u64 t, %1; cvt.u32.u64 %0, t; }"
        : "=r"(a) : "l"(p));
    return a;
}
__device__ __forceinline__ void cp16(uint32_t dst, const void* src) {
    asm volatile("cp.async.cg.shared.global [%0], [%1], 16;"
                 :: "r"(dst), "l"(src));
}
#define CP_COMMIT() asm volatile("cp.async.commit_group;" ::: "memory")
#define CP_WAIT(n)  asm volatile("cp.async.wait_group %0;" :: "n"(n) : "memory")

__device__ __forceinline__ void ldsm_x4(uint32_t* r, uint32_t addr) {
    asm volatile("ldmatrix.sync.aligned.m8n8.x4.shared.b16 {%0,%1,%2,%3}, [%4];"
        : "=r"(r[0]), "=r"(r[1]), "=r"(r[2]), "=r"(r[3]) : "r"(addr));
}
__device__ __forceinline__ void ldsm_x2(uint32_t* r, uint32_t addr) {
    asm volatile("ldmatrix.sync.aligned.m8n8.x2.shared.b16 {%0,%1}, [%2];"
        : "=r"(r[0]), "=r"(r[1]) : "r"(addr));
}
__device__ __forceinline__ void ldsm_x2t(uint32_t* r, uint32_t addr) {
    asm volatile("ldmatrix.sync.aligned.m8n8.x2.trans.shared.b16 {%0,%1}, [%2];"
        : "=r"(r[0]), "=r"(r[1]) : "r"(addr));
}
__device__ __forceinline__ void mma_bf16(float* c, const uint32_t* a, const uint32_t* b) {
    asm volatile("mma.sync.aligned.m16n8k16.row.col.f32.bf16.bf16.f32 "
        "{%0,%1,%2,%3}, {%4,%5,%6,%7}, {%8,%9}, {%0,%1,%2,%3};"
        : "+f"(c[0]), "+f"(c[1]), "+f"(c[2]), "+f"(c[3])
        : "r"(a[0]), "r"(a[1]), "r"(a[2]), "r"(a[3]), "r"(b[0]), "r"(b[1]));
}

__device__ __forceinline__ uint32_t pack_hi(float a, float b) {
    return ((uint32_t)__bfloat16_as_ushort(__float2bfloat16(b)) << 16) |
            (uint32_t)__bfloat16_as_ushort(__float2bfloat16(a));
}
__device__ __forceinline__ uint32_t pack_lo(float a, float b) {
    __nv_bfloat16 ha = __float2bfloat16(a), hb = __float2bfloat16(b);
    float la = a - __bfloat162float(ha), lb = b - __bfloat162float(hb);
    return ((uint32_t)__bfloat16_as_ushort(__float2bfloat16(lb)) << 16) |
            (uint32_t)__bfloat16_as_ushort(__float2bfloat16(la));
}
// fp32 pair -> (hi bf16x2, lo bf16x2); identical rounding to pack_hi/pack_lo
__device__ __forceinline__ void split2(float p0, float p1, uint32_t& hi, uint32_t& lo) {
    asm("cvt.rn.bf16x2.f32 %0, %1, %2;" : "=r"(hi) : "f"(p1), "f"(p0));
    float h0 = __uint_as_float(hi << 16);
    float h1 = __uint_as_float(hi & 0xffff0000u);
    float l0 = p0 - h0;
    float l1 = p1 - h1;
    asm("cvt.rn.bf16x2.f32 %0, %1, %2;" : "=r"(lo) : "f"(l1), "f"(l0));
}

// ---------------------------------------------------------------------------
// BIG-TILE projection GEMM (modes 0 and 3). Unchanged from R14 (proven).
// ---------------------------------------------------------------------------
template<int MODE>
__global__ __launch_bounds__(256)
void gemm_big(const __nv_bfloat16* __restrict__ Ahi_base,
              const __nv_bfloat16* __restrict__ Alo_base,
              const __nv_bfloat16* __restrict__ Bhi_base,
              const __nv_bfloat16* __restrict__ Blo_base,
              float* __restrict__ fout,
              __nv_bfloat16* __restrict__ ohi,
              __nv_bfloat16* __restrict__ olo,
              const float* __restrict__ bias,
              int by0) {
    constexpr int NSTAGE  = EMB / 32;           // 24
    constexpr int STAGES  = 3;
    constexpr int LDS     = 40;
    constexpr int A_BYTES = 256 * LDS * 2;
    constexpr int B_BYTES = 128 * LDS * 2;
    constexpr int STAGE_B = 2 * A_BYTES + 2 * B_BYTES;

    extern __shared__ __align__(16) char dynsmem[];

    const int tid  = threadIdx.x;
    const int lane = tid & 31;
    const int wid  = tid >> 5;
    const int wm   = wid & 3;
    const int wn   = wid >> 2;
    const int l15  = lane & 15;
    const int bx = blockIdx.x, by = blockIdx.y + by0;

    const __nv_bfloat16* Ah = Ahi_base + (long long)by * 256 * EMB;
    const __nv_bfloat16* Al = Alo_base + (long long)by * 256 * EMB;
    const __nv_bfloat16* Bh = Bhi_base + (long long)bx * 128 * EMB;
    const __nv_bfloat16* Bl = Blo_base + (long long)bx * 128 * EMB;

    const int arow = tid >> 2;
    const int acol = (tid & 3) * 8;

    const uint32_t sb = smem_u32(dynsmem);

    auto issue = [&](int s) {
        const uint32_t base = sb + (uint32_t)(s % STAGES) * STAGE_B;
        const long long k0 = (long long)s * 32;
        #pragma unroll
        for (int it = 0; it < 4; it++) {
            const int r = arow + it * 64;
            const uint32_t d = base + (uint32_t)(r * LDS + acol) * 2;
            cp16(d,           Ah + (long long)r * EMB + k0 + acol);
            cp16(d + A_BYTES, Al + (long long)r * EMB + k0 + acol);
        }
        #pragma unroll
        for (int it = 0; it < 2; it++) {
            const int r = arow + it * 64;
            const uint32_t d = base + 2 * A_BYTES + (uint32_t)(r * LDS + acol) * 2;
            cp16(d,           Bh + (long long)r * EMB + k0 + acol);
            cp16(d + B_BYTES, Bl + (long long)r * EMB + k0 + acol);
        }
    };

    float acc[4][8][4];
    #pragma unroll
    for (int i = 0; i < 4; i++)
        #pragma unroll
        for (int j = 0; j < 8; j++)
            #pragma unroll
            for (int e = 0; e < 4; e++) acc[i][j][e] = 0.f;

    issue(0); CP_COMMIT();
    issue(1); CP_COMMIT();

    for (int s = 0; s < NSTAGE; s++) {
        CP_WAIT(1);
        __syncthreads();
        if (s + 2 < NSTAGE) issue(s + 2);
        CP_COMMIT();

        const uint32_t base = sb + (uint32_t)(s % STAGES) * STAGE_B;
        const uint32_t uAh = base;
        const uint32_t uAl = base + A_BYTES;
        const uint32_t uBh = base + 2 * A_BYTES;
        const uint32_t uBl = base + 2 * A_BYTES + B_BYTES;

        #pragma unroll
        for (int ks = 0; ks < 2; ks++) {
            uint32_t bh[8][2], bl[8][2];
            #pragma unroll
            for (int j = 0; j < 8; j++) {
                const int nr = wn * 64 + j * 8 + (l15 & 7);
                const int kc = ks * 16 + (l15 >> 3) * 8;
                const uint32_t off = (uint32_t)(nr * LDS + kc) * 2;
                ldsm_x2(bh[j], uBh + off);
                ldsm_x2(bl[j], uBl + off);
            }
            #pragma unroll
            for (int i = 0; i < 4; i++) {
                const int ar = wm * 64 + i * 16 + l15;
                const int ac = ks * 16 + (lane >> 4) * 8;
                const uint32_t aoff = (uint32_t)(ar * LDS + ac) * 2;
                uint32_t ah[4], al[4];
                ldsm_x4(ah, uAh + aoff);
                #pragma unroll
                for (int j = 0; j < 8; j++) mma_bf16(acc[i][j], ah, bh[j]);
                ldsm_x4(al, uAl + aoff);
                #pragma unroll
                for (int j = 0; j < 8; j++) mma_bf16(acc[i][j], ah, bl[j]);
                #pragma unroll
                for (int j = 0; j < 8; j++) mma_bf16(acc[i][j], al, bh[j]);
            }
        }
    }

    const int g = lane >> 2, t = lane & 3;
    #pragma unroll
    for (int i = 0; i < 4; i++) {
        const int m0 = by * 256 + wm * 64 + i * 16 + g;
        const int m1 = m0 + 8;
        #pragma unroll
        for (int j = 0; j < 8; j++) {
            const int n = bx * 128 + wn * 64 + j * 8 + 2 * t;
            const float c0 = acc[i][j][0], c1 = acc[i][j][1];
            const float c2 = acc[i][j][2], c3 = acc[i][j][3];
            if (MODE == 0) {
                long long o0 = (long long)m0 * QKVC + n;
                long long o1 = (long long)m1 * QKVC + n;
                *(uint32_t*)(ohi + o0) = pack_hi(c0, c1);
                *(uint32_t*)(olo + o0) = pack_lo(c0, c1);
                *(uint32_t*)(ohi + o1) = pack_hi(c2, c3);
                *(uint32_t*)(olo + o1) = pack_lo(c2, c3);
            } else {
                float2 w0 = { c0 + bias[n], c1 + bias[n + 1] };
                float2 w1 = { c2 + bias[n], c3 + bias[n + 1] };
                *(float2*)(fout + (long long)m0 * EMB + n) = w0;
                *(float2*)(fout + (long long)m1 * EMB + n) = w1;
            }
        }
    }
}

// ---------------------------------------------------------------------------
// FUSED attention: per CTA (z, 128 q-rows): S=Q K^T (3-term), p=exp (written
// unnormalized fp32 into attn), rowsum, O += P V (3-term, P converted from
// accumulator frags to A frags IN REGISTERS), then in-kernel normalization of
// attn rows and staged oh hi/lo output. 8 warps, each m16 x full n64.
// ---------------------------------------------------------------------------
#define LDSQ 72
#define STG_LDS 66

__global__ __launch_bounds__(256, 2)
void fused_attn(const __nv_bfloat16* __restrict__ Qhi,   // qkv hi
                const __nv_bfloat16* __restrict__ Qlo,   // qkv lo
                float* __restrict__ attn,
                __nv_bfloat16* __restrict__ ohi,
                __nv_bfloat16* __restrict__ olo,
                int z0) {
    constexpr int NCHUNK  = 16;
    constexpr int QBUF    = 128 * LDSQ * 2;     // 18432
    constexpr int KVBUF   = 64 * LDSQ * 2;      // 9216
    constexpr int STAGE_B = 4 * KVBUF;          // 36864 (Kh,Kl,Vh,Vl)
    constexpr int KV0     = 2 * QBUF;           // 36864

    extern __shared__ __align__(16) char dynsmem[];

    const int tid  = threadIdx.x;
    const int lane = tid & 31;
    const int wid  = tid >> 5;
    const int l15  = lane & 15;
    const int g    = lane >> 2;
    const int t    = lane & 3;
    const int by = blockIdx.x;
    const int bz = blockIdx.y + z0;
    const int bb = bz / NH, hh = bz % NH;

    const long long qrow0 = (long long)bb * SEQL + by * 128;
    const long long krow0 = (long long)bb * SEQL;
    float* attn_z = attn + (long long)bz * SEQL * SEQL;

    const uint32_t sb = smem_u32(dynsmem);

    // loaders
    const int lrow = tid >> 3;            // 0..31 base
    const int lc16 = (tid & 7);           // 16B chunk in 64-col row (8 per row)

    auto issueQ = [&]() {
        #pragma unroll
        for (int it = 0; it < 4; it++) {
            const int r = lrow + it * 32;     // 0..127
            const long long go = (qrow0 + r) * QKVC + hh * HD + lc16 * 8;
            const uint32_t d = sb + (uint32_t)(r * LDSQ + lc16 * 8) * 2;
            cp16(d,        Qhi + go);
            cp16(d + QBUF, Qlo + go);
        }
    };
    auto issueKV = [&](int c) {
        const uint32_t base = sb + KV0 + (uint32_t)(c & 1) * STAGE_B;
        #pragma unroll
        for (int it = 0; it < 2; it++) {
            const int r = lrow + it * 32;     // 0..63
            const long long gk = (krow0 + c * 64 + r) * QKVC + EMB + hh * HD + lc16 * 8;
            const long long gv = gk + EMB;
            const uint32_t d = base + (uint32_t)(r * LDSQ + lc16 * 8) * 2;
            cp16(d,             Qhi + gk);    // K hi
            cp16(d + KVBUF,     Qlo + gk);    // K lo
            cp16(d + 2 * KVBUF, Qhi + gv);    // V hi
            cp16(d + 3 * KVBUF, Qlo + gv);    // V lo
        }
    };

    float o_acc[8][4];
    #pragma unroll
    for (int n = 0; n < 8; n++)
        #pragma unroll
        for (int e = 0; e < 4; e++) o_acc[n][e] = 0.f;
    float rs0 = 0.f, rs1 = 0.f;

    issueQ(); issueKV(0); CP_COMMIT();
    issueKV(1); CP_COMMIT();

    const uint32_t uQh = sb;
    const uint32_t uQl = sb + QBUF;

    for (int c = 0; c < NCHUNK; c++) {
        CP_WAIT(1);
        __syncthreads();

        const uint32_t base = sb + KV0 + (uint32_t)(c & 1) * STAGE_B;
        const uint32_t uKh = base;
        const uint32_t uKl = base + KVBUF;
        const uint32_t uVh = base + 2 * KVBUF;
        const uint32_t uVl = base + 3 * KVBUF;

        // ---- S = Q K^T, 3-term ----
        float s_acc[8][4];
        #pragma unroll
        for (int n = 0; n < 8; n++)
            #pragma unroll
            for (int e = 0; e < 4; e++) s_acc[n][e] = 0.f;

        #pragma unroll
        for (int ks = 0; ks < 4; ks++) {
            const int ar = wid * 16 + l15;
            const int ac = ks * 16 + (lane >> 4) * 8;
            const uint32_t aoff = (uint32_t)(ar * LDSQ + ac) * 2;
            uint32_t ah[4], al[4];
            ldsm_x4(ah, uQh + aoff);
            ldsm_x4(al, uQl + aoff);
            #pragma unroll
            for (int j = 0; j < 8; j++) {
                const int nr = j * 8 + (l15 & 7);
                const int kc = ks * 16 + (l15 >> 3) * 8;
                const uint32_t off = (uint32_t)(nr * LDSQ + kc) * 2;
                uint32_t bh[2], bl[2];
                ldsm_x2(bh, uKh + off);
                ldsm_x2(bl, uKl + off);
                mma_bf16(s_acc[j], ah, bh);
                mma_bf16(s_acc[j], ah, bl);
                mma_bf16(s_acc[j], al, bh);
            }
        }

        // ---- p = exp, rowsum, store unnormalized fp32 P ----
        const int r0 = by * 128 + wid * 16 + g;
        #pragma unroll
        for (int j = 0; j < 8; j++) {
            float p0 = __expf(fmaf(s_acc[j][0], K_SCALE, -EXP_OFF));
            float p1 = __expf(fmaf(s_acc[j][1], K_SCALE, -EXP_OFF));
            float p2 = __expf(fmaf(s_acc[j][2], K_SCALE, -EXP_OFF));
            float p3 = __expf(fmaf(s_acc[j][3], K_SCALE, -EXP_OFF));
            rs0 += p0 + p1; rs1 += p2 + p3;
            s_acc[j][0] = p0; s_acc[j][1] = p1;
            s_acc[j][2] = p2; s_acc[j][3] = p3;
            const long long col = (long long)c * 64 + j * 8 + 2 * t;
            float2 w0 = { p0, p1 }, w1 = { p2, p3 };
            *(float2*)(attn_z + (long long)r0 * SEQL + col)       = w0;
            *(float2*)(attn_z + (long long)(r0 + 8) * SEQL + col) = w1;
        }

        // ---- O += P V, 3-term; P A-frags built from accumulator frags ----
        #pragma unroll
        for (int jp = 0; jp < 4; jp++) {
            uint32_t ah[4], al[4];
            split2(s_acc[2*jp][0],   s_acc[2*jp][1],   ah[0], al[0]);
            split2(s_acc[2*jp][2],   s_acc[2*jp][3],   ah[1], al[1]);
            split2(s_acc[2*jp+1][0], s_acc[2*jp+1][1], ah[2], al[2]);
            split2(s_acc[2*jp+1][2], s_acc[2*jp+1][3], ah[3], al[3]);
            #pragma unroll
            for (int n = 0; n < 8; n++) {
                const int kr = jp * 16 + l15;
                const uint32_t off = (uint32_t)(kr * LDSQ + n * 8) * 2;
                uint32_t bvh[2], bvl[2];
                ldsm_x2t(bvh, uVh + off);
                ldsm_x2t(bvl, uVl + off);
                mma_bf16(o_acc[n], ah, bvh);
                mma_bf16(o_acc[n], ah, bvl);
                mma_bf16(o_acc[n], al, bvh);
            }
        }

        __syncthreads();
        if (c + 2 < NCHUNK) issueKV(c + 2);
        CP_COMMIT();
    }

    // ---- rowsum reduce over quad ----
    rs0 += __shfl_xor_sync(0xffffffffu, rs0, 1);
    rs0 += __shfl_xor_sync(0xffffffffu, rs0, 2);
    rs1 += __shfl_xor_sync(0xffffffffu, rs1, 1);
    rs1 += __shfl_xor_sync(0xffffffffu, rs1, 2);
    const float inv0 = 1.0f / rs0;
    const float inv1 = 1.0f / rs1;

    // ---- publish per-row inv, normalize attn rows in place ----
    CP_WAIT(0);
    __syncthreads();
    float* sInv = (float*)dynsmem;                       // 128 floats
    if (t == 0) {
        sInv[wid * 16 + g]     = inv0;
        sInv[wid * 16 + g + 8] = inv1;
    }
    __threadfence_block();
    __syncwarp();

    #pragma unroll 1
    for (int r = 0; r < 16; r++) {
        const float iv = sInv[wid * 16 + r];
        float* row = attn_z + (long long)(by * 128 + wid * 16 + r) * SEQL;
        #pragma unroll
        for (int it = 0; it < 8; it++) {
            float4* p4 = (float4*)(row + it * 128 + lane * 4);
            float4 v = *p4;
            v.x *= iv; v.y *= iv; v.z *= iv; v.w *= iv;
            *p4 = v;
        }
    }

    // ---- oh epilogue: stage hi/lo in smem (after sInv), coalesced store ----
    __nv_bfloat16* sOh = (__nv_bfloat16*)(dynsmem + 512);
    __nv_bfloat16* sOl = sOh + 128 * STG_LDS;
    #pragma unroll
    for (int n = 0; n < 8; n++) {
        const int r0 = wid * 16 + g;
        const float v0 = o_acc[n][0] * inv0, v1 = o_acc[n][1] * inv0;
        const float v2 = o_acc[n][2] * inv1, v3 = o_acc[n][3] * inv1;
        const int nloc = n * 8 + 2 * t;
        *(uint32_t*)(sOh + r0 * STG_LDS + nloc)       = pack_hi(v0, v1);
        *(uint32_t*)(sOl + r0 * STG_LDS + nloc)       = pack_lo(v0, v1);
        *(uint32_t*)(sOh + (r0 + 8) * STG_LDS + nloc) = pack_hi(v2, v3);
        *(uint32_t*)(sOl + (r0 + 8) * STG_LDS + nloc) = pack_lo(v2, v3);
    }
    __syncthreads();

    #pragma unroll
    for (int k = 0; k < 16; k++) {
        const int idx  = tid + k * 256;
        const int row  = idx >> 5;
        const int word = idx & 31;
        const uint32_t wh = *(const uint32_t*)(sOh + row * STG_LDS + word * 2);
        const uint32_t wl = *(const uint32_t*)(sOl + row * STG_LDS + word * 2);
        long long go = ((qrow0 + by * 0 + (long long)(by * 0)) , 0LL); (void)go;
        long long gdst = (((long long)bb * SEQL + by * 128 + row) * EMB + hh * HD) + word * 2;
        *(uint32_t*)(ohi + gdst) = wh;
        *(uint32_t*)(olo + gdst) = wl;
    }
}

// ---------------------------------------------------------------------------
// fp32 -> bf16 hi/lo split
// ---------------------------------------------------------------------------
__global__ void split_hilo(const float* __restrict__ src,
                           __nv_bfloat16* __restrict__ hi,
                           __nv_bfloat16* __restrict__ lo, int n) {
    int i = blockIdx.x * 256 + threadIdx.x;
    if (i < n) {
        float v = src[i];
        __nv_bfloat16 h = __float2bfloat16(v);
        hi[i] = h;
        lo[i] = __float2bfloat16(v - __bfloat162float(h));
    }
}

// ---------------------------------------------------------------------------
// Launch: two independent batch-half pipelines: split(x half) -> m0 ->
// fused_attn -> m3(half). Weight splits on stream 0 gate m0 / m3.
// ---------------------------------------------------------------------------
extern "C" void kernel_launch(void* const* d_in, const int* in_sizes, int n_in,
                              void* d_out, int out_size) {
    (void)in_sizes; (void)n_in; (void)out_size;
    const float* x      = (const float*)d_in[0];
    const float* w_qkv  = (const float*)d_in[1];
    const float* w_proj = (const float*)d_in[2];
    const float* b_proj = (const float*)d_in[3];

    float* out  = (float*)d_out;
    float* attn = out + (long long)ROWS * EMB;

    __nv_bfloat16 *xh, *xl, *wqh, *wql, *wph, *wpl, *qh, *ql, *ohh, *ohl;
    cudaGetSymbolAddress((void**)&xh,  g_x_hi);    cudaGetSymbolAddress((void**)&xl,  g_x_lo);
    cudaGetSymbolAddress((void**)&wqh, g_wqkv_hi); cudaGetSymbolAddress((void**)&wql, g_wqkv_lo);
    cudaGetSymbolAddress((void**)&wph, g_wp_hi);   cudaGetSymbolAddress((void**)&wpl, g_wp_lo);
    cudaGetSymbolAddress((void**)&qh,  g_qkv_hi);  cudaGetSymbolAddress((void**)&ql,  g_qkv_lo);
    cudaGetSymbolAddress((void**)&ohh, g_oh_hi);   cudaGetSymbolAddress((void**)&ohl, g_oh_lo);

    constexpr int SMBIG = 3 * 61440;   // 184320
    constexpr int SMFA  = 2 * 18432 + 2 * 36864;  // 110592
    constexpr int HALF_X = ROWS * EMB / 2;

    static cudaStream_t sA = nullptr, sB = nullptr;
    static cudaEvent_t evWq = nullptr, evWp = nullptr, evA = nullptr, evB = nullptr;
    static bool init_done = false;
    if (!init_done) {
        cudaFuncSetAttribute(gemm_big<0>, cudaFuncAttributeMaxDynamicSharedMemorySize, SMBIG);
        cudaFuncSetAttribute(gemm_big<3>, cudaFuncAttributeMaxDynamicSharedMemorySize, SMBIG);
        cudaFuncSetAttribute(fused_attn, cudaFuncAttributeMaxDynamicSharedMemorySize, SMFA);
        cudaStreamCreateWithFlags(&sA, cudaStreamNonBlocking);
        cudaStreamCreateWithFlags(&sB, cudaStreamNonBlocking);
        cudaEventCreateWithFlags(&evWq, cudaEventDisableTiming);
        cudaEventCreateWithFlags(&evWp, cudaEventDisableTiming);
        cudaEventCreateWithFlags(&evA, cudaEventDisableTiming);
        cudaEventCreateWithFlags(&evB, cudaEventDisableTiming);
        init_done = true;
    }

    // s0: weight splits
    split_hilo<<<(QKVC*EMB + 255)/256, 256>>>(w_qkv, wqh, wql, QKVC*EMB);
    cudaEventRecord(evWq, 0);
    split_hilo<<<(EMB*EMB + 255)/256, 256>>>(w_proj, wph, wpl, EMB*EMB);
    cudaEventRecord(evWp, 0);

    // --- pipeline A: batches 0-3 ---
    split_hilo<<<(HALF_X + 255)/256, 256, 0, sA>>>(x, xh, xl, HALF_X);
    cudaStreamWaitEvent(sA, evWq, 0);
    gemm_big<0><<<dim3(QKVC/128, 16), 256, SMBIG, sA>>>(
        xh, xl, wqh, wql, nullptr, qh, ql, nullptr, 0);
    fused_attn<<<dim3(8, 48), 256, SMFA, sA>>>(qh, ql, attn, ohh, ohl, 0);
    cudaStreamWaitEvent(sA, evWp, 0);
    gemm_big<3><<<dim3(EMB/128, 16), 256, SMBIG, sA>>>(
        ohh, ohl, wph, wpl, out, nullptr, nullptr, b_proj, 0);
    cudaEventRecord(evA, sA);

    // --- pipeline B: batches 4-7 ---
    split_hilo<<<(HALF_X + 255)/256, 256, 0, sB>>>(x + HALF_X, xh + HALF_X, xl + HALF_X, HALF_X);
    cudaStreamWaitEvent(sB, evWq, 0);
    gemm_big<0><<<dim3(QKVC/128, 16), 256, SMBIG, sB>>>(
        xh, xl, wqh, wql, nullptr, qh, ql, nullptr, 16);
    fused_attn<<<dim3(8, 48), 256, SMFA, sB>>>(qh, ql, attn, ohh, ohl, 48);
    cudaStreamWaitEvent(sB, evWp, 0);
    gemm_big<3><<<dim3(EMB/128, 16), 256, SMBIG, sB>>>(
        ohh, ohl, wph, wpl, out, nullptr, nullptr, b_proj, 16);
    cudaEventRecord(evB, sB);

    // join into the caller's stream
    cudaStreamWaitEvent(0, evA, 0);
    cudaStreamWaitEvent(0, evB, 0);
}